// round 3
// baseline (speedup 1.0000x reference)
#include <cuda_runtime.h>
#include <cstdint>

#define B_  2
#define T_  2048
#define D_  1024
#define H_  16
#define DH_ 64
#define SCALE 0.125f   // 1/sqrt(64)

typedef unsigned long long u64;

// Scratch (device globals: allocation-free, graph-capture safe)
__device__ float g_Q[B_*H_*T_*DH_];   // [B,H,T,DH]
__device__ float g_K[B_*H_*T_*DH_];
__device__ float g_V[B_*H_*T_*DH_];
__device__ float g_A[B_*T_*D_];       // attention output, head-concat layout [B,T,D]

__device__ __forceinline__ float neg_inf() { return __int_as_float(0xff800000u); }

// ---- packed f32x2 helpers (Blackwell) ---------------------------------------
__device__ __forceinline__ u64 pk2(float lo, float hi) {
    u64 r; asm("mov.b64 %0, {%1, %2};" : "=l"(r) : "f"(lo), "f"(hi)); return r;
}
__device__ __forceinline__ void upk2(u64 v, float& lo, float& hi) {
    asm("mov.b64 {%0, %1}, %2;" : "=f"(lo), "=f"(hi) : "l"(v));
}
__device__ __forceinline__ u64 fma2(u64 a, u64 b, u64 c) {
    u64 d; asm("fma.rn.f32x2 %0, %1, %2, %3;" : "=l"(d) : "l"(a), "l"(b), "l"(c)); return d;
}
__device__ __forceinline__ u64 mul2(u64 a, u64 b) {
    u64 d; asm("mul.rn.f32x2 %0, %1, %2;" : "=l"(d) : "l"(a), "l"(b)); return d;
}
__device__ __forceinline__ u64 add2(u64 a, u64 b) {
    u64 d; asm("add.rn.f32x2 %0, %1, %2;" : "=l"(d) : "l"(a), "l"(b)); return d;
}

// ----------------------------------------------------------------------------
// Kernel 1: fused per-head QKV projection.
// grid: (T/128, H, B). block: 128 threads, one t-row per thread.
// x tile loaded (transposed) into shared ONCE; Wq/Wk/Wv cycled through one
// 16KB shared buffer across three phases.
// ----------------------------------------------------------------------------
__global__ __launch_bounds__(128) void qkv_kernel(
    const float* __restrict__ x,
    const float* __restrict__ Wq, const float* __restrict__ bq,
    const float* __restrict__ Wk, const float* __restrict__ bk,
    const float* __restrict__ Wv, const float* __restrict__ bv)
{
    __shared__ __align__(16) float Wsh[DH_*DH_];   // 16 KB
    __shared__ float xsh[DH_*128];                 // 32 KB (transposed: [d][tid])

    const int h = blockIdx.y;
    const int b = blockIdx.z;
    const int tid = threadIdx.x;
    const int t = blockIdx.x*128 + tid;

    // Load this thread's x row into transposed shared
    const float* xr = x + ((size_t)b*T_ + t)*D_ + h*DH_;
    #pragma unroll
    for (int i = 0; i < 16; i++) {
        float4 v = ((const float4*)xr)[i];
        xsh[(4*i+0)*128 + tid] = v.x;
        xsh[(4*i+1)*128 + tid] = v.y;
        xsh[(4*i+2)*128 + tid] = v.z;
        xsh[(4*i+3)*128 + tid] = v.w;
    }

    const int r = tid >> 1, half = tid & 1;

    for (int m = 0; m < 3; m++) {
        const float* W; const float* bias; float* outp;
        if (m == 0)      { W = Wq; bias = bq; outp = g_Q; }
        else if (m == 1) { W = Wk; bias = bk; outp = g_K; }
        else             { W = Wv; bias = bv; outp = g_V; }
        W += h*DH_*DH_; bias += h*DH_;

        __syncthreads();   // previous phase done reading Wsh (and xsh ready on m=0)
        {
            const float4* src = (const float4*)(W + r*DH_ + half*32);
            float4* dst = (float4*)(Wsh + r*DH_ + half*32);
            #pragma unroll
            for (int i = 0; i < 8; i++) dst[i] = src[i];
        }
        __syncthreads();

        u64 acc[32];
        #pragma unroll
        for (int e2 = 0; e2 < 32; e2++) acc[e2] = pk2(bias[2*e2], bias[2*e2+1]);

        #pragma unroll 4
        for (int d = 0; d < DH_; d++) {
            float xd = xsh[d*128 + tid];
            u64 xx = pk2(xd, xd);
            const ulonglong2* wrow = (const ulonglong2*)(Wsh + d*DH_);
            #pragma unroll
            for (int e4 = 0; e4 < 16; e4++) {
                ulonglong2 w = wrow[e4];
                acc[2*e4+0] = fma2(xx, w.x, acc[2*e4+0]);
                acc[2*e4+1] = fma2(xx, w.y, acc[2*e4+1]);
            }
        }

        float* op = outp + (((size_t)b*H_ + h)*T_ + t)*DH_;
        #pragma unroll
        for (int e4 = 0; e4 < 16; e4++) {
            ulonglong2 v; v.x = acc[2*e4]; v.y = acc[2*e4+1];
            ((ulonglong2*)op)[e4] = v;
        }
    }
}

// ----------------------------------------------------------------------------
// Kernel 2: causal flash attention, fp32, f32x2-packed.
// grid: (T/128, H, B). block: 128 threads, one q-row per thread.
// Reversed block-x mapping: heavy (diagonal) blocks launch first.
// ----------------------------------------------------------------------------
__global__ __launch_bounds__(128) void attn_kernel()
{
    __shared__ __align__(16) float Ksh[64*64];   // 16 KB
    __shared__ __align__(16) float Vsh[64*64];   // 16 KB

    const int h = blockIdx.y, b = blockIdx.z;
    const int bx = (int)gridDim.x - 1 - (int)blockIdx.x;   // heavy-first
    const int tid = threadIdx.x;
    const int q = bx*128 + tid;

    const float* Qp = g_Q + (((size_t)b*H_ + h)*T_ + q)*DH_;
    const float* Kb = g_K + (((size_t)b*H_ + h)*T_)*DH_;
    const float* Vb = g_V + (((size_t)b*H_ + h)*T_)*DH_;

    u64 qv2[32];
    #pragma unroll
    for (int i = 0; i < 16; i++) {
        ulonglong2 v = ((const ulonglong2*)Qp)[i];
        qv2[2*i] = v.x; qv2[2*i+1] = v.y;
    }
    u64 o2[32];
    u64 zz = pk2(0.f, 0.f);
    #pragma unroll
    for (int e2 = 0; e2 < 32; e2++) o2[e2] = zz;
    float mrow = neg_inf(), l = 0.f;

    const int nkt = bx*2 + 2;       // k-tiles covering causal extent of block
    const int r = tid >> 1, half = tid & 1;

    for (int kt = 0; kt < nkt; kt++) {
        __syncthreads();
        const float4* ks = (const float4*)(Kb + ((size_t)(kt*64 + r))*64 + half*32);
        const float4* vs = (const float4*)(Vb + ((size_t)(kt*64 + r))*64 + half*32);
        float4* kd = (float4*)(Ksh + r*64 + half*32);
        float4* vd = (float4*)(Vsh + r*64 + half*32);
        #pragma unroll
        for (int i = 0; i < 8; i++) { kd[i] = ks[i]; vd[i] = vs[i]; }
        __syncthreads();

        const int kg0 = kt*64;
        #pragma unroll 1
        for (int jc = 0; jc < 64; jc += 16) {
            float s16[16];
            // S = q . K^T for 16 keys (packed f32x2, 4 independent chains)
            #pragma unroll
            for (int jj = 0; jj < 16; jj++) {
                const ulonglong2* kr = (const ulonglong2*)(Ksh + (jc+jj)*64);
                u64 a0 = zz, a1 = zz, a2 = zz, a3 = zz;
                #pragma unroll
                for (int e4 = 0; e4 < 16; e4 += 2) {
                    ulonglong2 k0 = kr[e4];
                    ulonglong2 k1 = kr[e4+1];
                    a0 = fma2(qv2[2*e4+0], k0.x, a0);
                    a1 = fma2(qv2[2*e4+1], k0.y, a1);
                    a2 = fma2(qv2[2*e4+2], k1.x, a2);
                    a3 = fma2(qv2[2*e4+3], k1.y, a3);
                }
                u64 s01 = add2(a0, a1), s23 = add2(a2, a3);
                u64 s = add2(s01, s23);
                float lo, hi; upk2(s, lo, hi);
                s16[jj] = lo + hi;
            }
            // scale + causal mask + chunk max
            float mt = neg_inf();
            #pragma unroll
            for (int jj = 0; jj < 16; jj++) {
                float sv = s16[jj]*SCALE;
                if (kg0 + jc + jj > q) sv = neg_inf();
                s16[jj] = sv;
                mt = fmaxf(mt, sv);
            }
            float mn = fmaxf(mrow, mt);      // finite: key 0 <= q always hit first
            float corr = __expf(mrow - mn);
            float ps = 0.f;
            #pragma unroll
            for (int jj = 0; jj < 16; jj++) {
                float p = __expf(s16[jj] - mn);
                s16[jj] = p;
                ps += p;
            }
            l = l*corr + ps;
            u64 cc = pk2(corr, corr);
            #pragma unroll
            for (int e2 = 0; e2 < 32; e2++) o2[e2] = mul2(o2[e2], cc);
            // O += P V  (packed)
            #pragma unroll
            for (int jj = 0; jj < 16; jj++) {
                u64 pp = pk2(s16[jj], s16[jj]);
                const ulonglong2* vr = (const ulonglong2*)(Vsh + (jc+jj)*64);
                #pragma unroll
                for (int e4 = 0; e4 < 16; e4++) {
                    ulonglong2 v = vr[e4];
                    o2[2*e4+0] = fma2(pp, v.x, o2[2*e4+0]);
                    o2[2*e4+1] = fma2(pp, v.y, o2[2*e4+1]);
                }
            }
            mrow = mn;
        }
    }

    float inv = 1.f / l;
    u64 ii = pk2(inv, inv);
    float* op = g_A + ((size_t)b*T_ + q)*D_ + h*DH_;   // head-concat layout
    #pragma unroll
    for (int e4 = 0; e4 < 16; e4++) {
        ulonglong2 v;
        v.x = mul2(o2[2*e4+0], ii);
        v.y = mul2(o2[2*e4+1], ii);
        ((ulonglong2*)op)[e4] = v;
    }
}

// ----------------------------------------------------------------------------
// Kernel 3: output projection  out = g_A @ Wo + bo  (f32x2-packed)
// grid: (B*T/128, D/64). block: 128 threads, one row x 64 cols per thread.
// ----------------------------------------------------------------------------
__global__ __launch_bounds__(128) void oproj_kernel(
    const float* __restrict__ Wo, const float* __restrict__ bo,
    float* __restrict__ out)
{
    __shared__ __align__(16) float Wsh[64*64];   // 16 KB
    __shared__ float xsh[64*128];                // 32 KB (transposed)

    const int tid = threadIdx.x;
    const int row = blockIdx.x*128 + tid;        // flattened b*T + t
    const int n0 = blockIdx.y*64;

    u64 acc[32];
    #pragma unroll
    for (int e2 = 0; e2 < 32; e2++) acc[e2] = pk2(bo[n0 + 2*e2], bo[n0 + 2*e2 + 1]);

    const int r = tid >> 1, half = tid & 1;
    for (int k0 = 0; k0 < D_; k0 += 64) {
        __syncthreads();
        // Wo[k0+r][n0 + half*32 ...]
        const float4* ws = (const float4*)(Wo + (size_t)(k0 + r)*D_ + n0 + half*32);
        float4* wd = (float4*)(Wsh + r*64 + half*32);
        #pragma unroll
        for (int i = 0; i < 8; i++) wd[i] = ws[i];
        // x chunk for this thread's row, transposed into shared
        const float* xr = g_A + (size_t)row*D_ + k0;
        #pragma unroll
        for (int i = 0; i < 16; i++) {
            float4 v = ((const float4*)xr)[i];
            xsh[(4*i+0)*128 + tid] = v.x;
            xsh[(4*i+1)*128 + tid] = v.y;
            xsh[(4*i+2)*128 + tid] = v.z;
            xsh[(4*i+3)*128 + tid] = v.w;
        }
        __syncthreads();

        #pragma unroll 4
        for (int d = 0; d < 64; d++) {
            float xd = xsh[d*128 + tid];
            u64 xx = pk2(xd, xd);
            const ulonglong2* wrow = (const ulonglong2*)(Wsh + d*64);
            #pragma unroll
            for (int e4 = 0; e4 < 16; e4++) {
                ulonglong2 w = wrow[e4];
                acc[2*e4+0] = fma2(xx, w.x, acc[2*e4+0]);
                acc[2*e4+1] = fma2(xx, w.y, acc[2*e4+1]);
            }
        }
    }

    float* op = out + (size_t)row*D_ + n0;
    #pragma unroll
    for (int e4 = 0; e4 < 16; e4++) {
        ulonglong2 v; v.x = acc[2*e4]; v.y = acc[2*e4+1];
        ((ulonglong2*)op)[e4] = v;
    }
}

// ----------------------------------------------------------------------------
extern "C" void kernel_launch(void* const* d_in, const int* in_sizes, int n_in,
                              void* d_out, int out_size)
{
    const float* x  = (const float*)d_in[0];
    const float* Wq = (const float*)d_in[1];
    const float* bq = (const float*)d_in[2];
    const float* Wk = (const float*)d_in[3];
    const float* bk = (const float*)d_in[4];
    const float* Wv = (const float*)d_in[5];
    const float* bv = (const float*)d_in[6];
    const float* Wo = (const float*)d_in[7];
    const float* bo = (const float*)d_in[8];
    float* out = (float*)d_out;

    qkv_kernel<<<dim3(T_/128, H_, B_), 128>>>(x, Wq, bq, Wk, bk, Wv, bv);
    attn_kernel<<<dim3(T_/128, H_, B_), 128>>>();
    oproj_kernel<<<dim3((B_*T_)/128, D_/64), 128>>>(Wo, bo, out);
}

// round 4
// speedup vs baseline: 2.5853x; 2.5853x over previous
#include <cuda_runtime.h>
#include <cstdint>

#define B_  2
#define T_  2048
#define D_  1024
#define H_  16
#define DH_ 64
#define SCALE 0.125f   // 1/sqrt(64)
#define QMUL  0.1803368801111136f   // SCALE * log2(e)

typedef unsigned int u32;
typedef unsigned long long u64;

// Scratch (device globals: allocation-free, graph-capture safe)
__device__ float g_Q[B_*H_*T_*DH_];   // [B,H,T,DH]
__device__ float g_K[B_*H_*T_*DH_];
__device__ float g_V[B_*H_*T_*DH_];
__device__ float g_A[B_*T_*D_];       // attention output, head-concat [B,T,D]

// ---- helpers ---------------------------------------------------------------
__device__ __forceinline__ float tf32f(float x) {
    u32 r; asm("cvt.rna.tf32.f32 %0, %1;" : "=r"(r) : "f"(x));
    return __uint_as_float(r);
}
__device__ __forceinline__ u32 tf32u(float x) {
    u32 r; asm("cvt.rna.tf32.f32 %0, %1;" : "=r"(r) : "f"(x));
    return r;
}
__device__ __forceinline__ float ex2(float x) {
    float r; asm("ex2.approx.ftz.f32 %0, %1;" : "=f"(r) : "f"(x));
    return r;
}

#define MMA_TF32(d, a0, a1, a2, a3, b0, b1) \
    asm volatile("mma.sync.aligned.m16n8k8.row.col.f32.tf32.tf32.f32 " \
        "{%0,%1,%2,%3}, {%4,%5,%6,%7}, {%8,%9}, {%0,%1,%2,%3};" \
        : "+f"((d)[0]), "+f"((d)[1]), "+f"((d)[2]), "+f"((d)[3]) \
        : "r"(a0), "r"(a1), "r"(a2), "r"(a3), "r"(b0), "r"(b1))

// Column interleave inside each 8-group: e -> (e>>3)*8 + (e&3)*2 + ((e>>2)&1)
// so that fragment pairs (c, c+4) sit at (2c, 2c+1) -> one LDS.64.
#define LSTRIDE 74

// ----------------------------------------------------------------------------
// Kernel 1: fused per-head QKV projection (fp32 scalar; latency-bound, small)
// ----------------------------------------------------------------------------
__global__ __launch_bounds__(128) void qkv_kernel(
    const float* __restrict__ x,
    const float* __restrict__ Wq, const float* __restrict__ bq,
    const float* __restrict__ Wk, const float* __restrict__ bk,
    const float* __restrict__ Wv, const float* __restrict__ bv)
{
    __shared__ __align__(16) float Wsh[DH_*DH_];
    __shared__ float xsh[DH_*128];

    const int h = blockIdx.y;
    const int b = blockIdx.z;
    const int tid = threadIdx.x;
    const int t = blockIdx.x*128 + tid;

    const float* xr = x + ((size_t)b*T_ + t)*D_ + h*DH_;
    #pragma unroll
    for (int i = 0; i < 16; i++) {
        float4 v = ((const float4*)xr)[i];
        xsh[(4*i+0)*128 + tid] = v.x;
        xsh[(4*i+1)*128 + tid] = v.y;
        xsh[(4*i+2)*128 + tid] = v.z;
        xsh[(4*i+3)*128 + tid] = v.w;
    }

    const int r = tid >> 1, half = tid & 1;

    for (int m = 0; m < 3; m++) {
        const float* W; const float* bias; float* outp;
        if (m == 0)      { W = Wq; bias = bq; outp = g_Q; }
        else if (m == 1) { W = Wk; bias = bk; outp = g_K; }
        else             { W = Wv; bias = bv; outp = g_V; }
        W += h*DH_*DH_; bias += h*DH_;

        __syncthreads();
        {
            const float4* src = (const float4*)(W + r*DH_ + half*32);
            float4* dst = (float4*)(Wsh + r*DH_ + half*32);
            #pragma unroll
            for (int i = 0; i < 8; i++) dst[i] = src[i];
        }
        __syncthreads();

        float acc[DH_];
        #pragma unroll
        for (int e = 0; e < DH_; e++) acc[e] = bias[e];

        #pragma unroll 4
        for (int d = 0; d < DH_; d++) {
            float xd = xsh[d*128 + tid];
            #pragma unroll
            for (int e4 = 0; e4 < 16; e4++) {
                float4 w = ((const float4*)(Wsh + d*DH_))[e4];
                acc[4*e4+0] += xd*w.x;
                acc[4*e4+1] += xd*w.y;
                acc[4*e4+2] += xd*w.z;
                acc[4*e4+3] += xd*w.w;
            }
        }

        float* op = outp + (((size_t)b*H_ + h)*T_ + t)*DH_;
        #pragma unroll
        for (int e4 = 0; e4 < 16; e4++) {
            float4 v = make_float4(acc[4*e4], acc[4*e4+1], acc[4*e4+2], acc[4*e4+3]);
            ((float4*)op)[e4] = v;
        }
    }
}

// ----------------------------------------------------------------------------
// Kernel 2: causal flash attention with tf32 mma.sync.
// grid (16,16,2) reversed-x; CTA 256 thr = 8 warps x 16 q-rows; K-tiles of 64.
// ----------------------------------------------------------------------------
__global__ __launch_bounds__(256, 2) void attn_kernel()
{
    extern __shared__ float sm[];
    float* Qsh = sm;                  // 128 x 74, tf32, scaled by QMUL
    float* Ksh = sm + 128*LSTRIDE;    // 64 x 74, tf32
    float* Vsh = sm + 192*LSTRIDE;    // 64 x 74, transposed [d][jperm], tf32

    const int h = blockIdx.y, b = blockIdx.z;
    const int bx = (int)gridDim.x - 1 - (int)blockIdx.x;   // heavy-first
    const int q0 = bx*128;
    const int tid = threadIdx.x;
    const int w = tid >> 5, lane = tid & 31;
    const int g = lane >> 2, c = lane & 3;

    const float* Qb = g_Q + (((size_t)b*H_ + h)*T_)*DH_;
    const float* Kb = g_K + (((size_t)b*H_ + h)*T_)*DH_;
    const float* Vb = g_V + (((size_t)b*H_ + h)*T_)*DH_;

    // Stage Q tile (scaled, tf32, column-pair interleaved)
    {
        const int row = tid >> 1, half = (tid & 1)*32;
        const float4* src = (const float4*)(Qb + (size_t)(q0+row)*DH_ + half);
        float* dst = Qsh + row*LSTRIDE;
        #pragma unroll
        for (int i = 0; i < 8; i++) {
            float4 v = src[i];
            int e0 = half + i*4;
            int base = ((e0>>3)<<3) + ((e0>>2)&1);
            dst[base+0] = tf32f(v.x*QMUL);
            dst[base+2] = tf32f(v.y*QMUL);
            dst[base+4] = tf32f(v.z*QMUL);
            dst[base+6] = tf32f(v.w*QMUL);
        }
    }

    const int qw = q0 + w*16;           // warp's first q row (global)
    float s[8][4];
    float o[8][4];
    #pragma unroll
    for (int nt = 0; nt < 8; nt++) { o[nt][0]=o[nt][1]=o[nt][2]=o[nt][3]=0.f; }
    float m0 = -1e30f, m1 = -1e30f, l0 = 0.f, l1 = 0.f;

    const int nkt = bx*2 + 2;
    const int jload = tid >> 2, qq = tid & 3;
    const int jp = ((jload>>3)<<3) + ((jload&3)<<1) + ((jload>>2)&1);

    for (int kt = 0; kt < nkt; kt++) {
        __syncthreads();
        // load K (interleaved) and V (transposed+interleaved) tiles, cvt tf32
        {
            const float* krow = Kb + (size_t)(kt*64 + jload)*DH_ + qq*16;
            const float* vrow = Vb + (size_t)(kt*64 + jload)*DH_ + qq*16;
            float* kdst = Ksh + jload*LSTRIDE;
            #pragma unroll
            for (int i4 = 0; i4 < 4; i4++) {
                float4 kv = ((const float4*)krow)[i4];
                float4 vv = ((const float4*)vrow)[i4];
                int e0 = qq*16 + i4*4;
                int kb = ((e0>>3)<<3) + ((e0>>2)&1);
                kdst[kb+0] = tf32f(kv.x); kdst[kb+2] = tf32f(kv.y);
                kdst[kb+4] = tf32f(kv.z); kdst[kb+6] = tf32f(kv.w);
                Vsh[(e0+0)*LSTRIDE + jp] = tf32f(vv.x);
                Vsh[(e0+1)*LSTRIDE + jp] = tf32f(vv.y);
                Vsh[(e0+2)*LSTRIDE + jp] = tf32f(vv.z);
                Vsh[(e0+3)*LSTRIDE + jp] = tf32f(vv.w);
            }
        }
        __syncthreads();

        if (kt*64 > qw + 15) continue;   // tile fully above diagonal for warp

        // ---- S = Q K^T (scores already in log2 domain via QMUL) ----
        #pragma unroll
        for (int nt = 0; nt < 8; nt++) { s[nt][0]=s[nt][1]=s[nt][2]=s[nt][3]=0.f; }
        const float* qbase = Qsh + (w*16 + g)*LSTRIDE + 2*c;
        #pragma unroll
        for (int k8 = 0; k8 < 8; k8++) {
            uint2 a02 = *(const uint2*)(qbase + k8*8);
            uint2 a13 = *(const uint2*)(qbase + 8*LSTRIDE + k8*8);
            #pragma unroll
            for (int nt = 0; nt < 8; nt++) {
                uint2 bb = *(const uint2*)(Ksh + (nt*8+g)*LSTRIDE + k8*8 + 2*c);
                MMA_TF32(s[nt], a02.x, a13.x, a02.y, a13.y, bb.x, bb.y);
            }
        }

        // ---- causal mask (only near-diagonal tiles) ----
        const int r0 = qw + g, r1 = r0 + 8;
        if (kt*64 + 63 > qw) {
            const int colb = kt*64 + 2*c;
            #pragma unroll
            for (int nt = 0; nt < 8; nt++) {
                int c0 = colb + nt*8, c1 = c0 + 1;
                if (c0 > r0) s[nt][0] = -1e30f;
                if (c1 > r0) s[nt][1] = -1e30f;
                if (c0 > r1) s[nt][2] = -1e30f;
                if (c1 > r1) s[nt][3] = -1e30f;
            }
        }

        // ---- online softmax (base 2) ----
        float rm0 = -1e30f, rm1 = -1e30f;
        #pragma unroll
        for (int nt = 0; nt < 8; nt++) {
            rm0 = fmaxf(rm0, fmaxf(s[nt][0], s[nt][1]));
            rm1 = fmaxf(rm1, fmaxf(s[nt][2], s[nt][3]));
        }
        rm0 = fmaxf(rm0, __shfl_xor_sync(0xffffffffu, rm0, 1));
        rm0 = fmaxf(rm0, __shfl_xor_sync(0xffffffffu, rm0, 2));
        rm1 = fmaxf(rm1, __shfl_xor_sync(0xffffffffu, rm1, 1));
        rm1 = fmaxf(rm1, __shfl_xor_sync(0xffffffffu, rm1, 2));
        float mn0 = fmaxf(m0, rm0), mn1 = fmaxf(m1, rm1);
        float corr0 = ex2(m0 - mn0), corr1 = ex2(m1 - mn1);
        m0 = mn0; m1 = mn1;
        float ps0 = 0.f, ps1 = 0.f;
        #pragma unroll
        for (int nt = 0; nt < 8; nt++) {
            s[nt][0] = ex2(s[nt][0] - mn0); ps0 += s[nt][0];
            s[nt][1] = ex2(s[nt][1] - mn0); ps0 += s[nt][1];
            s[nt][2] = ex2(s[nt][2] - mn1); ps1 += s[nt][2];
            s[nt][3] = ex2(s[nt][3] - mn1); ps1 += s[nt][3];
        }
        l0 = l0*corr0 + ps0;
        l1 = l1*corr1 + ps1;
        #pragma unroll
        for (int nt = 0; nt < 8; nt++) {
            o[nt][0] *= corr0; o[nt][1] *= corr0;
            o[nt][2] *= corr1; o[nt][3] *= corr1;
        }

        // ---- O += P V  (P C-frags -> A-frags via quad shuffles) ----
        const int srcA = (lane & ~3) | (c >> 1);
        const int srcB = srcA + 2;
        const bool odd = (c & 1);
        #pragma unroll
        for (int jt = 0; jt < 8; jt++) {
            u32 p0 = tf32u(s[jt][0]), p1 = tf32u(s[jt][1]);
            u32 p2 = tf32u(s[jt][2]), p3 = tf32u(s[jt][3]);
            u32 x0 = __shfl_sync(0xffffffffu, p0, srcA);
            u32 x1 = __shfl_sync(0xffffffffu, p1, srcA);
            u32 x2 = __shfl_sync(0xffffffffu, p2, srcA);
            u32 x3 = __shfl_sync(0xffffffffu, p3, srcA);
            u32 y0 = __shfl_sync(0xffffffffu, p0, srcB);
            u32 y1 = __shfl_sync(0xffffffffu, p1, srcB);
            u32 y2 = __shfl_sync(0xffffffffu, p2, srcB);
            u32 y3 = __shfl_sync(0xffffffffu, p3, srcB);
            u32 pa0 = odd ? x1 : x0;   // P[g,   jt*8+c  ]
            u32 pa1 = odd ? x3 : x2;   // P[g+8, jt*8+c  ]
            u32 pa2 = odd ? y1 : y0;   // P[g,   jt*8+c+4]
            u32 pa3 = odd ? y3 : y2;   // P[g+8, jt*8+c+4]
            #pragma unroll
            for (int nt = 0; nt < 8; nt++) {
                uint2 bb = *(const uint2*)(Vsh + (nt*8+g)*LSTRIDE + jt*8 + 2*c);
                MMA_TF32(o[nt], pa0, pa1, pa2, pa3, bb.x, bb.y);
            }
        }
    }

    // ---- epilogue: finish l across quad, normalize, store ----
    l0 += __shfl_xor_sync(0xffffffffu, l0, 1);
    l0 += __shfl_xor_sync(0xffffffffu, l0, 2);
    l1 += __shfl_xor_sync(0xffffffffu, l1, 1);
    l1 += __shfl_xor_sync(0xffffffffu, l1, 2);
    const float inv0 = 1.f/l0, inv1 = 1.f/l1;
    float* Ob = g_A + ((size_t)b*T_)*D_ + h*DH_;
    const int r0 = qw + g, r1 = r0 + 8;
    #pragma unroll
    for (int nt = 0; nt < 8; nt++) {
        int cc = nt*8 + 2*c;
        *(float2*)(Ob + (size_t)r0*D_ + cc) = make_float2(o[nt][0]*inv0, o[nt][1]*inv0);
        *(float2*)(Ob + (size_t)r1*D_ + cc) = make_float2(o[nt][2]*inv1, o[nt][3]*inv1);
    }
}

// ----------------------------------------------------------------------------
// Kernel 3: output projection, tf32 mma GEMM: out = g_A @ Wo + bo
// grid (32,16); CTA 128 thr = 4 warps x 2 m-tiles; 128x64 tile, K-chunks of 64.
// ----------------------------------------------------------------------------
__global__ __launch_bounds__(128, 4) void oproj_kernel(
    const float* __restrict__ Wo, const float* __restrict__ bo,
    float* __restrict__ out)
{
    extern __shared__ float sm[];
    float* Ash = sm;                  // 128 x 74, tf32, col-interleaved
    float* Bsh = sm + 128*LSTRIDE;    // 64 x 74 = WoT [n][kperm], tf32

    const int tid = threadIdx.x;
    const int w = tid >> 5, lane = tid & 31;
    const int g = lane >> 2, c = lane & 3;
    const int r0 = blockIdx.x*128;
    const int n0 = blockIdx.y*64;

    float o[2][8][4];
    #pragma unroll
    for (int mt = 0; mt < 2; mt++)
        #pragma unroll
        for (int nt = 0; nt < 8; nt++)
            o[mt][nt][0]=o[mt][nt][1]=o[mt][nt][2]=o[mt][nt][3]=0.f;

    const int krow = tid >> 1, nh = (tid & 1)*32;
    const int kp = ((krow>>3)<<3) + ((krow&3)<<1) + ((krow>>2)&1);

    for (int k0 = 0; k0 < D_; k0 += 64) {
        __syncthreads();
        {   // A tile: one row per thread
            const float4* src = (const float4*)(g_A + (size_t)(r0+tid)*D_ + k0);
            float* dst = Ash + tid*LSTRIDE;
            #pragma unroll
            for (int i4 = 0; i4 < 16; i4++) {
                float4 v = src[i4];
                int e0 = i4*4;
                int bb = ((e0>>3)<<3) + ((e0>>2)&1);
                dst[bb+0] = tf32f(v.x); dst[bb+2] = tf32f(v.y);
                dst[bb+4] = tf32f(v.z); dst[bb+6] = tf32f(v.w);
            }
        }
        {   // B tile: Wo[k0+krow][n0+nh..] -> Bsh[n][kperm]
            const float4* src = (const float4*)(Wo + (size_t)(k0+krow)*D_ + n0 + nh);
            #pragma unroll
            for (int i4 = 0; i4 < 8; i4++) {
                float4 v = src[i4];
                int nn = nh + i4*4;
                Bsh[(nn+0)*LSTRIDE + kp] = tf32f(v.x);
                Bsh[(nn+1)*LSTRIDE + kp] = tf32f(v.y);
                Bsh[(nn+2)*LSTRIDE + kp] = tf32f(v.z);
                Bsh[(nn+3)*LSTRIDE + kp] = tf32f(v.w);
            }
        }
        __syncthreads();

        const float* abase = Ash + (w*32 + g)*LSTRIDE + 2*c;
        #pragma unroll
        for (int k8 = 0; k8 < 8; k8++) {
            uint2 a02_0 = *(const uint2*)(abase + k8*8);
            uint2 a13_0 = *(const uint2*)(abase +  8*LSTRIDE + k8*8);
            uint2 a02_1 = *(const uint2*)(abase + 16*LSTRIDE + k8*8);
            uint2 a13_1 = *(const uint2*)(abase + 24*LSTRIDE + k8*8);
            #pragma unroll
            for (int nt = 0; nt < 8; nt++) {
                uint2 bb = *(const uint2*)(Bsh + (nt*8+g)*LSTRIDE + k8*8 + 2*c);
                MMA_TF32(o[0][nt], a02_0.x, a13_0.x, a02_0.y, a13_0.y, bb.x, bb.y);
                MMA_TF32(o[1][nt], a02_1.x, a13_1.x, a02_1.y, a13_1.y, bb.x, bb.y);
            }
        }
    }

    #pragma unroll
    for (int mt = 0; mt < 2; mt++) {
        const int rr0 = r0 + w*32 + mt*16 + g;
        #pragma unroll
        for (int nt = 0; nt < 8; nt++) {
            int cc = n0 + nt*8 + 2*c;
            float b0v = bo[cc], b1v = bo[cc+1];
            *(float2*)(out + (size_t)rr0*D_ + cc) =
                make_float2(o[mt][nt][0]+b0v, o[mt][nt][1]+b1v);
            *(float2*)(out + (size_t)(rr0+8)*D_ + cc) =
                make_float2(o[mt][nt][2]+b0v, o[mt][nt][3]+b1v);
        }
    }
}

// ----------------------------------------------------------------------------
extern "C" void kernel_launch(void* const* d_in, const int* in_sizes, int n_in,
                              void* d_out, int out_size)
{
    (void)in_sizes; (void)n_in; (void)out_size;
    const float* x  = (const float*)d_in[0];
    const float* Wq = (const float*)d_in[1];
    const float* bq = (const float*)d_in[2];
    const float* Wk = (const float*)d_in[3];
    const float* bk = (const float*)d_in[4];
    const float* Wv = (const float*)d_in[5];
    const float* bv = (const float*)d_in[6];
    const float* Wo = (const float*)d_in[7];
    const float* bo = (const float*)d_in[8];
    float* out = (float*)d_out;

    const int attn_smem  = 256*LSTRIDE*4;   // 75776 B
    const int oproj_smem = 192*LSTRIDE*4;   // 56832 B
    cudaFuncSetAttribute(attn_kernel,  cudaFuncAttributeMaxDynamicSharedMemorySize, attn_smem);
    cudaFuncSetAttribute(oproj_kernel, cudaFuncAttributeMaxDynamicSharedMemorySize, oproj_smem);

    qkv_kernel<<<dim3(T_/128, H_, B_), 128>>>(x, Wq, bq, Wk, bk, Wv, bv);
    attn_kernel<<<dim3(T_/128, H_, B_), 256, attn_smem>>>();
    oproj_kernel<<<dim3((B_*T_)/128, D_/64), 128, oproj_smem>>>(Wo, bo, out);
}

// round 5
// speedup vs baseline: 2.7925x; 1.0801x over previous
#include <cuda_runtime.h>
#include <cstdint>

#define B_  2
#define T_  2048
#define D_  1024
#define H_  16
#define DH_ 64
#define SCALE 0.125f   // 1/sqrt(64)
#define QMUL  0.1803368801111136f   // SCALE * log2(e)

typedef unsigned int u32;
typedef unsigned long long u64;

// Scratch (device globals: allocation-free, graph-capture safe)
__device__ float g_Q[B_*H_*T_*DH_];   // [B,H,T,DH]
__device__ float g_K[B_*H_*T_*DH_];
__device__ float g_V[B_*H_*T_*DH_];
__device__ float g_A[B_*T_*D_];       // attention output, head-concat [B,T,D]

// ---- helpers ---------------------------------------------------------------
__device__ __forceinline__ float tf32f(float x) {
    u32 r; asm("cvt.rna.tf32.f32 %0, %1;" : "=r"(r) : "f"(x));
    return __uint_as_float(r);
}
__device__ __forceinline__ u32 tf32u(float x) {
    u32 r; asm("cvt.rna.tf32.f32 %0, %1;" : "=r"(r) : "f"(x));
    return r;
}
__device__ __forceinline__ float ex2(float x) {
    float r; asm("ex2.approx.ftz.f32 %0, %1;" : "=f"(r) : "f"(x));
    return r;
}

#define MMA_TF32(d, a0, a1, a2, a3, b0, b1) \
    asm volatile("mma.sync.aligned.m16n8k8.row.col.f32.tf32.tf32.f32 " \
        "{%0,%1,%2,%3}, {%4,%5,%6,%7}, {%8,%9}, {%0,%1,%2,%3};" \
        : "+f"((d)[0]), "+f"((d)[1]), "+f"((d)[2]), "+f"((d)[3]) \
        : "r"(a0), "r"(a1), "r"(a2), "r"(a3), "r"(b0), "r"(b1))

// Column interleave inside each 8-group: e -> (e>>3)*8 + (e&3)*2 + ((e>>2)&1)
// so that fragment pairs (c, c+4) sit at (2c, 2c+1) -> one LDS.64.
#define LSTRIDE 74

// ----------------------------------------------------------------------------
// Kernel 1: fused per-head QKV projection, tf32 MMA.
// grid (T/128, H, B); 128 thr = 4 warps x 32 rows. One x tile staged once;
// Wq/Wk/Wv cycled through the B buffer across 3 phases.
// ----------------------------------------------------------------------------
__global__ __launch_bounds__(128, 4) void qkv_kernel(
    const float* __restrict__ x,
    const float* __restrict__ Wq, const float* __restrict__ bq,
    const float* __restrict__ Wk, const float* __restrict__ bk,
    const float* __restrict__ Wv, const float* __restrict__ bv)
{
    extern __shared__ float sm[];
    float* Ash = sm;                  // 128 x 74  (x tile, tf32, col-interleaved)
    float* Bsh = sm + 128*LSTRIDE;    // 64 x 74   (W^T: [e][dperm], tf32)

    const int h = blockIdx.y;
    const int b = blockIdx.z;
    const int tid = threadIdx.x;
    const int w = tid >> 5, lane = tid & 31;
    const int g = lane >> 2, c = lane & 3;
    const int t0 = blockIdx.x*128;

    // Stage x tile: one row per thread
    {
        const float4* src = (const float4*)(x + ((size_t)b*T_ + t0 + tid)*D_ + h*DH_);
        float* dst = Ash + tid*LSTRIDE;
        #pragma unroll
        for (int i4 = 0; i4 < 16; i4++) {
            float4 v = src[i4];
            int e0 = i4*4;
            int bb = ((e0>>3)<<3) + ((e0>>2)&1);
            dst[bb+0] = tf32f(v.x); dst[bb+2] = tf32f(v.y);
            dst[bb+4] = tf32f(v.z); dst[bb+6] = tf32f(v.w);
        }
    }

    const int krow = tid >> 1, nh = (tid & 1)*32;
    const int kp = ((krow>>3)<<3) + ((krow&3)<<1) + ((krow>>2)&1);

    for (int m = 0; m < 3; m++) {
        const float* W; const float* bias; float* outp;
        if (m == 0)      { W = Wq; bias = bq; outp = g_Q; }
        else if (m == 1) { W = Wk; bias = bk; outp = g_K; }
        else             { W = Wv; bias = bv; outp = g_V; }
        W += h*DH_*DH_; bias += h*DH_;

        __syncthreads();   // Ash ready (m=0) / previous phase done reading Bsh
        {   // B tile: W[d=krow][e=nh..] -> Bsh[e][dperm]
            const float4* src = (const float4*)(W + (size_t)krow*DH_ + nh);
            #pragma unroll
            for (int i4 = 0; i4 < 8; i4++) {
                float4 v = src[i4];
                int nn = nh + i4*4;
                Bsh[(nn+0)*LSTRIDE + kp] = tf32f(v.x);
                Bsh[(nn+1)*LSTRIDE + kp] = tf32f(v.y);
                Bsh[(nn+2)*LSTRIDE + kp] = tf32f(v.z);
                Bsh[(nn+3)*LSTRIDE + kp] = tf32f(v.w);
            }
        }
        __syncthreads();

        float o[2][8][4];
        #pragma unroll
        for (int mt = 0; mt < 2; mt++)
            #pragma unroll
            for (int nt = 0; nt < 8; nt++)
                o[mt][nt][0]=o[mt][nt][1]=o[mt][nt][2]=o[mt][nt][3]=0.f;

        const float* abase = Ash + (w*32 + g)*LSTRIDE + 2*c;
        #pragma unroll
        for (int k8 = 0; k8 < 8; k8++) {
            uint2 a02_0 = *(const uint2*)(abase + k8*8);
            uint2 a13_0 = *(const uint2*)(abase +  8*LSTRIDE + k8*8);
            uint2 a02_1 = *(const uint2*)(abase + 16*LSTRIDE + k8*8);
            uint2 a13_1 = *(const uint2*)(abase + 24*LSTRIDE + k8*8);
            #pragma unroll
            for (int nt = 0; nt < 8; nt++) {
                uint2 bb = *(const uint2*)(Bsh + (nt*8+g)*LSTRIDE + k8*8 + 2*c);
                MMA_TF32(o[0][nt], a02_0.x, a13_0.x, a02_0.y, a13_0.y, bb.x, bb.y);
                MMA_TF32(o[1][nt], a02_1.x, a13_1.x, a02_1.y, a13_1.y, bb.x, bb.y);
            }
        }

        float* Obase = outp + (((size_t)b*H_ + h)*T_ + t0)*DH_;
        #pragma unroll
        for (int mt = 0; mt < 2; mt++) {
            const int rr0 = w*32 + mt*16 + g;
            #pragma unroll
            for (int nt = 0; nt < 8; nt++) {
                int cc = nt*8 + 2*c;
                float b0v = bias[cc], b1v = bias[cc+1];
                *(float2*)(Obase + (size_t)rr0*DH_ + cc) =
                    make_float2(o[mt][nt][0]+b0v, o[mt][nt][1]+b1v);
                *(float2*)(Obase + (size_t)(rr0+8)*DH_ + cc) =
                    make_float2(o[mt][nt][2]+b0v, o[mt][nt][3]+b1v);
            }
        }
    }
}

// ----------------------------------------------------------------------------
// Kernel 2: causal flash attention with tf32 mma.sync.
// grid (16,16,2) reversed-x; CTA 256 thr = 8 warps x 16 q-rows; K-tiles of 64.
// ----------------------------------------------------------------------------
__global__ __launch_bounds__(256, 2) void attn_kernel()
{
    extern __shared__ float sm[];
    float* Qsh = sm;                  // 128 x 74, tf32, scaled by QMUL
    float* Ksh = sm + 128*LSTRIDE;    // 64 x 74, tf32
    float* Vsh = sm + 192*LSTRIDE;    // 64 x 74, transposed [d][jperm], tf32

    const int h = blockIdx.y, b = blockIdx.z;
    const int bx = (int)gridDim.x - 1 - (int)blockIdx.x;   // heavy-first
    const int q0 = bx*128;
    const int tid = threadIdx.x;
    const int w = tid >> 5, lane = tid & 31;
    const int g = lane >> 2, c = lane & 3;

    const float* Qb = g_Q + (((size_t)b*H_ + h)*T_)*DH_;
    const float* Kb = g_K + (((size_t)b*H_ + h)*T_)*DH_;
    const float* Vb = g_V + (((size_t)b*H_ + h)*T_)*DH_;

    // Stage Q tile (scaled, tf32, column-pair interleaved)
    {
        const int row = tid >> 1, half = (tid & 1)*32;
        const float4* src = (const float4*)(Qb + (size_t)(q0+row)*DH_ + half);
        float* dst = Qsh + row*LSTRIDE;
        #pragma unroll
        for (int i = 0; i < 8; i++) {
            float4 v = src[i];
            int e0 = half + i*4;
            int base = ((e0>>3)<<3) + ((e0>>2)&1);
            dst[base+0] = tf32f(v.x*QMUL);
            dst[base+2] = tf32f(v.y*QMUL);
            dst[base+4] = tf32f(v.z*QMUL);
            dst[base+6] = tf32f(v.w*QMUL);
        }
    }

    const int qw = q0 + w*16;           // warp's first q row (global)
    float s[8][4];
    float o[8][4];
    #pragma unroll
    for (int nt = 0; nt < 8; nt++) { o[nt][0]=o[nt][1]=o[nt][2]=o[nt][3]=0.f; }
    float m0 = -1e30f, m1 = -1e30f, l0 = 0.f, l1 = 0.f;

    const int nkt = bx*2 + 2;
    const int jload = tid >> 2, qq = tid & 3;
    const int jp = ((jload>>3)<<3) + ((jload&3)<<1) + ((jload>>2)&1);

    for (int kt = 0; kt < nkt; kt++) {
        __syncthreads();
        // load K (interleaved) and V (transposed+interleaved) tiles, cvt tf32
        {
            const float* krow = Kb + (size_t)(kt*64 + jload)*DH_ + qq*16;
            const float* vrow = Vb + (size_t)(kt*64 + jload)*DH_ + qq*16;
            float* kdst = Ksh + jload*LSTRIDE;
            #pragma unroll
            for (int i4 = 0; i4 < 4; i4++) {
                float4 kv = ((const float4*)krow)[i4];
                float4 vv = ((const float4*)vrow)[i4];
                int e0 = qq*16 + i4*4;
                int kb = ((e0>>3)<<3) + ((e0>>2)&1);
                kdst[kb+0] = tf32f(kv.x); kdst[kb+2] = tf32f(kv.y);
                kdst[kb+4] = tf32f(kv.z); kdst[kb+6] = tf32f(kv.w);
                Vsh[(e0+0)*LSTRIDE + jp] = tf32f(vv.x);
                Vsh[(e0+1)*LSTRIDE + jp] = tf32f(vv.y);
                Vsh[(e0+2)*LSTRIDE + jp] = tf32f(vv.z);
                Vsh[(e0+3)*LSTRIDE + jp] = tf32f(vv.w);
            }
        }
        __syncthreads();

        if (kt*64 > qw + 15) continue;   // tile fully above diagonal for warp

        // ---- S = Q K^T (scores already in log2 domain via QMUL) ----
        #pragma unroll
        for (int nt = 0; nt < 8; nt++) { s[nt][0]=s[nt][1]=s[nt][2]=s[nt][3]=0.f; }
        const float* qbase = Qsh + (w*16 + g)*LSTRIDE + 2*c;
        #pragma unroll
        for (int k8 = 0; k8 < 8; k8++) {
            uint2 a02 = *(const uint2*)(qbase + k8*8);
            uint2 a13 = *(const uint2*)(qbase + 8*LSTRIDE + k8*8);
            #pragma unroll
            for (int nt = 0; nt < 8; nt++) {
                uint2 bb = *(const uint2*)(Ksh + (nt*8+g)*LSTRIDE + k8*8 + 2*c);
                MMA_TF32(s[nt], a02.x, a13.x, a02.y, a13.y, bb.x, bb.y);
            }
        }

        // ---- causal mask (only near-diagonal tiles) ----
        const int r0 = qw + g, r1 = r0 + 8;
        if (kt*64 + 63 > qw) {
            const int colb = kt*64 + 2*c;
            #pragma unroll
            for (int nt = 0; nt < 8; nt++) {
                int c0 = colb + nt*8, c1 = c0 + 1;
                if (c0 > r0) s[nt][0] = -1e30f;
                if (c1 > r0) s[nt][1] = -1e30f;
                if (c0 > r1) s[nt][2] = -1e30f;
                if (c1 > r1) s[nt][3] = -1e30f;
            }
        }

        // ---- online softmax (base 2) ----
        float rm0 = -1e30f, rm1 = -1e30f;
        #pragma unroll
        for (int nt = 0; nt < 8; nt++) {
            rm0 = fmaxf(rm0, fmaxf(s[nt][0], s[nt][1]));
            rm1 = fmaxf(rm1, fmaxf(s[nt][2], s[nt][3]));
        }
        rm0 = fmaxf(rm0, __shfl_xor_sync(0xffffffffu, rm0, 1));
        rm0 = fmaxf(rm0, __shfl_xor_sync(0xffffffffu, rm0, 2));
        rm1 = fmaxf(rm1, __shfl_xor_sync(0xffffffffu, rm1, 1));
        rm1 = fmaxf(rm1, __shfl_xor_sync(0xffffffffu, rm1, 2));
        float mn0 = fmaxf(m0, rm0), mn1 = fmaxf(m1, rm1);
        float corr0 = ex2(m0 - mn0), corr1 = ex2(m1 - mn1);
        m0 = mn0; m1 = mn1;
        float ps0 = 0.f, ps1 = 0.f;
        #pragma unroll
        for (int nt = 0; nt < 8; nt++) {
            s[nt][0] = ex2(s[nt][0] - mn0); ps0 += s[nt][0];
            s[nt][1] = ex2(s[nt][1] - mn0); ps0 += s[nt][1];
            s[nt][2] = ex2(s[nt][2] - mn1); ps1 += s[nt][2];
            s[nt][3] = ex2(s[nt][3] - mn1); ps1 += s[nt][3];
        }
        l0 = l0*corr0 + ps0;
        l1 = l1*corr1 + ps1;
        #pragma unroll
        for (int nt = 0; nt < 8; nt++) {
            o[nt][0] *= corr0; o[nt][1] *= corr0;
            o[nt][2] *= corr1; o[nt][3] *= corr1;
        }

        // ---- O += P V  (P C-frags -> A-frags via quad shuffles) ----
        const int srcA = (lane & ~3) | (c >> 1);
        const int srcB = srcA + 2;
        const bool odd = (c & 1);
        #pragma unroll
        for (int jt = 0; jt < 8; jt++) {
            u32 p0 = tf32u(s[jt][0]), p1 = tf32u(s[jt][1]);
            u32 p2 = tf32u(s[jt][2]), p3 = tf32u(s[jt][3]);
            u32 x0 = __shfl_sync(0xffffffffu, p0, srcA);
            u32 x1 = __shfl_sync(0xffffffffu, p1, srcA);
            u32 x2 = __shfl_sync(0xffffffffu, p2, srcA);
            u32 x3 = __shfl_sync(0xffffffffu, p3, srcA);
            u32 y0 = __shfl_sync(0xffffffffu, p0, srcB);
            u32 y1 = __shfl_sync(0xffffffffu, p1, srcB);
            u32 y2 = __shfl_sync(0xffffffffu, p2, srcB);
            u32 y3 = __shfl_sync(0xffffffffu, p3, srcB);
            u32 pa0 = odd ? x1 : x0;   // P[g,   jt*8+c  ]
            u32 pa1 = odd ? x3 : x2;   // P[g+8, jt*8+c  ]
            u32 pa2 = odd ? y1 : y0;   // P[g,   jt*8+c+4]
            u32 pa3 = odd ? y3 : y2;   // P[g+8, jt*8+c+4]
            #pragma unroll
            for (int nt = 0; nt < 8; nt++) {
                uint2 bb = *(const uint2*)(Vsh + (nt*8+g)*LSTRIDE + jt*8 + 2*c);
                MMA_TF32(o[nt], pa0, pa1, pa2, pa3, bb.x, bb.y);
            }
        }
    }

    // ---- epilogue: finish l across quad, normalize, store ----
    l0 += __shfl_xor_sync(0xffffffffu, l0, 1);
    l0 += __shfl_xor_sync(0xffffffffu, l0, 2);
    l1 += __shfl_xor_sync(0xffffffffu, l1, 1);
    l1 += __shfl_xor_sync(0xffffffffu, l1, 2);
    const float inv0 = 1.f/l0, inv1 = 1.f/l1;
    float* Ob = g_A + ((size_t)b*T_)*D_ + h*DH_;
    const int r0 = qw + g, r1 = r0 + 8;
    #pragma unroll
    for (int nt = 0; nt < 8; nt++) {
        int cc = nt*8 + 2*c;
        *(float2*)(Ob + (size_t)r0*D_ + cc) = make_float2(o[nt][0]*inv0, o[nt][1]*inv0);
        *(float2*)(Ob + (size_t)r1*D_ + cc) = make_float2(o[nt][2]*inv1, o[nt][3]*inv1);
    }
}

// ----------------------------------------------------------------------------
// Kernel 3: output projection, tf32 mma GEMM: out = g_A @ Wo + bo
// grid (32,16); CTA 128 thr = 4 warps x 2 m-tiles; 128x64 tile, K-chunks of 64.
// ----------------------------------------------------------------------------
__global__ __launch_bounds__(128, 4) void oproj_kernel(
    const float* __restrict__ Wo, const float* __restrict__ bo,
    float* __restrict__ out)
{
    extern __shared__ float sm[];
    float* Ash = sm;                  // 128 x 74, tf32, col-interleaved
    float* Bsh = sm + 128*LSTRIDE;    // 64 x 74 = WoT [n][kperm], tf32

    const int tid = threadIdx.x;
    const int w = tid >> 5, lane = tid & 31;
    const int g = lane >> 2, c = lane & 3;
    const int r0 = blockIdx.x*128;
    const int n0 = blockIdx.y*64;

    float o[2][8][4];
    #pragma unroll
    for (int mt = 0; mt < 2; mt++)
        #pragma unroll
        for (int nt = 0; nt < 8; nt++)
            o[mt][nt][0]=o[mt][nt][1]=o[mt][nt][2]=o[mt][nt][3]=0.f;

    const int krow = tid >> 1, nh = (tid & 1)*32;
    const int kp = ((krow>>3)<<3) + ((krow&3)<<1) + ((krow>>2)&1);

    for (int k0 = 0; k0 < D_; k0 += 64) {
        __syncthreads();
        {   // A tile: one row per thread
            const float4* src = (const float4*)(g_A + (size_t)(r0+tid)*D_ + k0);
            float* dst = Ash + tid*LSTRIDE;
            #pragma unroll
            for (int i4 = 0; i4 < 16; i4++) {
                float4 v = src[i4];
                int e0 = i4*4;
                int bb = ((e0>>3)<<3) + ((e0>>2)&1);
                dst[bb+0] = tf32f(v.x); dst[bb+2] = tf32f(v.y);
                dst[bb+4] = tf32f(v.z); dst[bb+6] = tf32f(v.w);
            }
        }
        {   // B tile: Wo[k0+krow][n0+nh..] -> Bsh[n][kperm]
            const float4* src = (const float4*)(Wo + (size_t)(k0+krow)*D_ + n0 + nh);
            #pragma unroll
            for (int i4 = 0; i4 < 8; i4++) {
                float4 v = src[i4];
                int nn = nh + i4*4;
                Bsh[(nn+0)*LSTRIDE + kp] = tf32f(v.x);
                Bsh[(nn+1)*LSTRIDE + kp] = tf32f(v.y);
                Bsh[(nn+2)*LSTRIDE + kp] = tf32f(v.z);
                Bsh[(nn+3)*LSTRIDE + kp] = tf32f(v.w);
            }
        }
        __syncthreads();

        const float* abase = Ash + (w*32 + g)*LSTRIDE + 2*c;
        #pragma unroll
        for (int k8 = 0; k8 < 8; k8++) {
            uint2 a02_0 = *(const uint2*)(abase + k8*8);
            uint2 a13_0 = *(const uint2*)(abase +  8*LSTRIDE + k8*8);
            uint2 a02_1 = *(const uint2*)(abase + 16*LSTRIDE + k8*8);
            uint2 a13_1 = *(const uint2*)(abase + 24*LSTRIDE + k8*8);
            #pragma unroll
            for (int nt = 0; nt < 8; nt++) {
                uint2 bb = *(const uint2*)(Bsh + (nt*8+g)*LSTRIDE + k8*8 + 2*c);
                MMA_TF32(o[0][nt], a02_0.x, a13_0.x, a02_0.y, a13_0.y, bb.x, bb.y);
                MMA_TF32(o[1][nt], a02_1.x, a13_1.x, a02_1.y, a13_1.y, bb.x, bb.y);
            }
        }
    }

    #pragma unroll
    for (int mt = 0; mt < 2; mt++) {
        const int rr0 = r0 + w*32 + mt*16 + g;
        #pragma unroll
        for (int nt = 0; nt < 8; nt++) {
            int cc = n0 + nt*8 + 2*c;
            float b0v = bo[cc], b1v = bo[cc+1];
            *(float2*)(out + (size_t)rr0*D_ + cc) =
                make_float2(o[mt][nt][0]+b0v, o[mt][nt][1]+b1v);
            *(float2*)(out + (size_t)(rr0+8)*D_ + cc) =
                make_float2(o[mt][nt][2]+b0v, o[mt][nt][3]+b1v);
        }
    }
}

// ----------------------------------------------------------------------------
extern "C" void kernel_launch(void* const* d_in, const int* in_sizes, int n_in,
                              void* d_out, int out_size)
{
    (void)in_sizes; (void)n_in; (void)out_size;
    const float* x  = (const float*)d_in[0];
    const float* Wq = (const float*)d_in[1];
    const float* bq = (const float*)d_in[2];
    const float* Wk = (const float*)d_in[3];
    const float* bk = (const float*)d_in[4];
    const float* Wv = (const float*)d_in[5];
    const float* bv = (const float*)d_in[6];
    const float* Wo = (const float*)d_in[7];
    const float* bo = (const float*)d_in[8];
    float* out = (float*)d_out;

    const int qkv_smem   = 192*LSTRIDE*4;   // 56832 B
    const int attn_smem  = 256*LSTRIDE*4;   // 75776 B
    const int oproj_smem = 192*LSTRIDE*4;   // 56832 B
    cudaFuncSetAttribute(qkv_kernel,   cudaFuncAttributeMaxDynamicSharedMemorySize, qkv_smem);
    cudaFuncSetAttribute(attn_kernel,  cudaFuncAttributeMaxDynamicSharedMemorySize, attn_smem);
    cudaFuncSetAttribute(oproj_kernel, cudaFuncAttributeMaxDynamicSharedMemorySize, oproj_smem);

    qkv_kernel<<<dim3(T_/128, H_, B_), 128, qkv_smem>>>(x, Wq, bq, Wk, bk, Wv, bv);
    attn_kernel<<<dim3(T_/128, H_, B_), 256, attn_smem>>>();
    oproj_kernel<<<dim3((B_*T_)/128, D_/64), 128, oproj_smem>>>(Wo, bo, out);
}

// round 6
// speedup vs baseline: 2.8486x; 1.0201x over previous
#include <cuda_runtime.h>
#include <cstdint>

#define B_  2
#define T_  2048
#define D_  1024
#define H_  16
#define DH_ 64
#define SCALE 0.125f   // 1/sqrt(64)
#define QMUL  0.1803368801111136f   // SCALE * log2(e)

typedef unsigned int u32;
typedef unsigned long long u64;

// Scratch (device globals: allocation-free, graph-capture safe)
__device__ float g_Q[B_*H_*T_*DH_];   // [B,H,T,DH]
__device__ float g_K[B_*H_*T_*DH_];
__device__ float g_V[B_*H_*T_*DH_];
__device__ float g_A[B_*T_*D_];       // attention output, head-concat [B,T,D]

// ---- helpers ---------------------------------------------------------------
__device__ __forceinline__ float tf32f(float x) {
    u32 r; asm("cvt.rna.tf32.f32 %0, %1;" : "=r"(r) : "f"(x));
    return __uint_as_float(r);
}
__device__ __forceinline__ u32 tf32u(float x) {
    u32 r; asm("cvt.rna.tf32.f32 %0, %1;" : "=r"(r) : "f"(x));
    return r;
}
__device__ __forceinline__ float ex2(float x) {
    float r; asm("ex2.approx.ftz.f32 %0, %1;" : "=f"(r) : "f"(x));
    return r;
}

#define MMA_TF32(d, a0, a1, a2, a3, b0, b1) \
    asm volatile("mma.sync.aligned.m16n8k8.row.col.f32.tf32.tf32.f32 " \
        "{%0,%1,%2,%3}, {%4,%5,%6,%7}, {%8,%9}, {%0,%1,%2,%3};" \
        : "+f"((d)[0]), "+f"((d)[1]), "+f"((d)[2]), "+f"((d)[3]) \
        : "r"(a0), "r"(a1), "r"(a2), "r"(a3), "r"(b0), "r"(b1))

// Column interleave inside each 8-group: e -> (e>>3)*8 + (e&3)*2 + ((e>>2)&1)
// so that fragment pairs (c, c+4) sit at (2c, 2c+1) -> one LDS.64.
#define LSTRIDE 74

// ----------------------------------------------------------------------------
// Kernel 1: fused per-head QKV projection, tf32 MMA.
// grid (T/128, H, B); 128 thr = 4 warps x 32 rows. One x tile staged once;
// Wq/Wk/Wv cycled through the B buffer across 3 phases.
// ----------------------------------------------------------------------------
__global__ __launch_bounds__(128, 4) void qkv_kernel(
    const float* __restrict__ x,
    const float* __restrict__ Wq, const float* __restrict__ bq,
    const float* __restrict__ Wk, const float* __restrict__ bk,
    const float* __restrict__ Wv, const float* __restrict__ bv)
{
    extern __shared__ float sm[];
    float* Ash = sm;                  // 128 x 74  (x tile, tf32, col-interleaved)
    float* Bsh = sm + 128*LSTRIDE;    // 64 x 74   (W^T: [e][dperm], tf32)

    const int h = blockIdx.y;
    const int b = blockIdx.z;
    const int tid = threadIdx.x;
    const int w = tid >> 5, lane = tid & 31;
    const int g = lane >> 2, c = lane & 3;
    const int t0 = blockIdx.x*128;

    // Stage x tile: one row per thread
    {
        const float4* src = (const float4*)(x + ((size_t)b*T_ + t0 + tid)*D_ + h*DH_);
        float* dst = Ash + tid*LSTRIDE;
        #pragma unroll
        for (int i4 = 0; i4 < 16; i4++) {
            float4 v = src[i4];
            int e0 = i4*4;
            int bb = ((e0>>3)<<3) + ((e0>>2)&1);
            dst[bb+0] = tf32f(v.x); dst[bb+2] = tf32f(v.y);
            dst[bb+4] = tf32f(v.z); dst[bb+6] = tf32f(v.w);
        }
    }

    const int krow = tid >> 1, nh = (tid & 1)*32;
    const int kp = ((krow>>3)<<3) + ((krow&3)<<1) + ((krow>>2)&1);

    for (int m = 0; m < 3; m++) {
        const float* W; const float* bias; float* outp;
        if (m == 0)      { W = Wq; bias = bq; outp = g_Q; }
        else if (m == 1) { W = Wk; bias = bk; outp = g_K; }
        else             { W = Wv; bias = bv; outp = g_V; }
        W += h*DH_*DH_; bias += h*DH_;

        __syncthreads();   // Ash ready (m=0) / previous phase done reading Bsh
        {   // B tile: W[d=krow][e=nh..] -> Bsh[e][dperm]
            const float4* src = (const float4*)(W + (size_t)krow*DH_ + nh);
            #pragma unroll
            for (int i4 = 0; i4 < 8; i4++) {
                float4 v = src[i4];
                int nn = nh + i4*4;
                Bsh[(nn+0)*LSTRIDE + kp] = tf32f(v.x);
                Bsh[(nn+1)*LSTRIDE + kp] = tf32f(v.y);
                Bsh[(nn+2)*LSTRIDE + kp] = tf32f(v.z);
                Bsh[(nn+3)*LSTRIDE + kp] = tf32f(v.w);
            }
        }
        __syncthreads();

        float o[2][8][4];
        #pragma unroll
        for (int mt = 0; mt < 2; mt++)
            #pragma unroll
            for (int nt = 0; nt < 8; nt++)
                o[mt][nt][0]=o[mt][nt][1]=o[mt][nt][2]=o[mt][nt][3]=0.f;

        const float* abase = Ash + (w*32 + g)*LSTRIDE + 2*c;
        #pragma unroll
        for (int k8 = 0; k8 < 8; k8++) {
            uint2 a02_0 = *(const uint2*)(abase + k8*8);
            uint2 a13_0 = *(const uint2*)(abase +  8*LSTRIDE + k8*8);
            uint2 a02_1 = *(const uint2*)(abase + 16*LSTRIDE + k8*8);
            uint2 a13_1 = *(const uint2*)(abase + 24*LSTRIDE + k8*8);
            #pragma unroll
            for (int nt = 0; nt < 8; nt++) {
                uint2 bb = *(const uint2*)(Bsh + (nt*8+g)*LSTRIDE + k8*8 + 2*c);
                MMA_TF32(o[0][nt], a02_0.x, a13_0.x, a02_0.y, a13_0.y, bb.x, bb.y);
                MMA_TF32(o[1][nt], a02_1.x, a13_1.x, a02_1.y, a13_1.y, bb.x, bb.y);
            }
        }

        float* Obase = outp + (((size_t)b*H_ + h)*T_ + t0)*DH_;
        #pragma unroll
        for (int mt = 0; mt < 2; mt++) {
            const int rr0 = w*32 + mt*16 + g;
            #pragma unroll
            for (int nt = 0; nt < 8; nt++) {
                int cc = nt*8 + 2*c;
                float b0v = bias[cc], b1v = bias[cc+1];
                *(float2*)(Obase + (size_t)rr0*DH_ + cc) =
                    make_float2(o[mt][nt][0]+b0v, o[mt][nt][1]+b1v);
                *(float2*)(Obase + (size_t)(rr0+8)*DH_ + cc) =
                    make_float2(o[mt][nt][2]+b0v, o[mt][nt][3]+b1v);
            }
        }
    }
}

// ----------------------------------------------------------------------------
// Kernel 2: causal flash attention with tf32 mma.sync.
// grid (16,16,2) reversed-x; CTA 256 thr = 8 warps x 16 q-rows; K-tiles of 64.
// ----------------------------------------------------------------------------
__global__ __launch_bounds__(256, 2) void attn_kernel()
{
    extern __shared__ float sm[];
    float* Qsh = sm;                  // 128 x 74, tf32, scaled by QMUL
    float* Ksh = sm + 128*LSTRIDE;    // 64 x 74, tf32
    float* Vsh = sm + 192*LSTRIDE;    // 64 x 74, transposed [d][jperm], tf32

    const int h = blockIdx.y, b = blockIdx.z;
    const int bx = (int)gridDim.x - 1 - (int)blockIdx.x;   // heavy-first
    const int q0 = bx*128;
    const int tid = threadIdx.x;
    const int w = tid >> 5, lane = tid & 31;
    const int g = lane >> 2, c = lane & 3;

    const float* Qb = g_Q + (((size_t)b*H_ + h)*T_)*DH_;
    const float* Kb = g_K + (((size_t)b*H_ + h)*T_)*DH_;
    const float* Vb = g_V + (((size_t)b*H_ + h)*T_)*DH_;

    // Stage Q tile (scaled, tf32, column-pair interleaved)
    {
        const int row = tid >> 1, half = (tid & 1)*32;
        const float4* src = (const float4*)(Qb + (size_t)(q0+row)*DH_ + half);
        float* dst = Qsh + row*LSTRIDE;
        #pragma unroll
        for (int i = 0; i < 8; i++) {
            float4 v = src[i];
            int e0 = half + i*4;
            int base = ((e0>>3)<<3) + ((e0>>2)&1);
            dst[base+0] = tf32f(v.x*QMUL);
            dst[base+2] = tf32f(v.y*QMUL);
            dst[base+4] = tf32f(v.z*QMUL);
            dst[base+6] = tf32f(v.w*QMUL);
        }
    }

    const int qw = q0 + w*16;           // warp's first q row (global)
    float s[8][4];
    float o[8][4];
    #pragma unroll
    for (int nt = 0; nt < 8; nt++) { o[nt][0]=o[nt][1]=o[nt][2]=o[nt][3]=0.f; }
    float m0 = -1e30f, m1 = -1e30f, l0 = 0.f, l1 = 0.f;

    const int nkt = bx*2 + 2;
    const int jload = tid >> 2, qq = tid & 3;
    const int jp = ((jload>>3)<<3) + ((jload&3)<<1) + ((jload>>2)&1);

    for (int kt = 0; kt < nkt; kt++) {
        __syncthreads();
        // load K (interleaved) and V (transposed+interleaved) tiles, cvt tf32
        {
            const float* krow = Kb + (size_t)(kt*64 + jload)*DH_ + qq*16;
            const float* vrow = Vb + (size_t)(kt*64 + jload)*DH_ + qq*16;
            float* kdst = Ksh + jload*LSTRIDE;
            #pragma unroll
            for (int i4 = 0; i4 < 4; i4++) {
                float4 kv = ((const float4*)krow)[i4];
                float4 vv = ((const float4*)vrow)[i4];
                int e0 = qq*16 + i4*4;
                int kb = ((e0>>3)<<3) + ((e0>>2)&1);
                kdst[kb+0] = tf32f(kv.x); kdst[kb+2] = tf32f(kv.y);
                kdst[kb+4] = tf32f(kv.z); kdst[kb+6] = tf32f(kv.w);
                Vsh[(e0+0)*LSTRIDE + jp] = tf32f(vv.x);
                Vsh[(e0+1)*LSTRIDE + jp] = tf32f(vv.y);
                Vsh[(e0+2)*LSTRIDE + jp] = tf32f(vv.z);
                Vsh[(e0+3)*LSTRIDE + jp] = tf32f(vv.w);
            }
        }
        __syncthreads();

        if (kt*64 > qw + 15) continue;   // tile fully above diagonal for warp

        // ---- S = Q K^T (scores already in log2 domain via QMUL) ----
        #pragma unroll
        for (int nt = 0; nt < 8; nt++) { s[nt][0]=s[nt][1]=s[nt][2]=s[nt][3]=0.f; }
        const float* qbase = Qsh + (w*16 + g)*LSTRIDE + 2*c;
        #pragma unroll
        for (int k8 = 0; k8 < 8; k8++) {
            uint2 a02 = *(const uint2*)(qbase + k8*8);
            uint2 a13 = *(const uint2*)(qbase + 8*LSTRIDE + k8*8);
            #pragma unroll
            for (int nt = 0; nt < 8; nt++) {
                uint2 bb = *(const uint2*)(Ksh + (nt*8+g)*LSTRIDE + k8*8 + 2*c);
                MMA_TF32(s[nt], a02.x, a13.x, a02.y, a13.y, bb.x, bb.y);
            }
        }

        // ---- causal mask (only near-diagonal tiles) ----
        const int r0 = qw + g, r1 = r0 + 8;
        if (kt*64 + 63 > qw) {
            const int colb = kt*64 + 2*c;
            #pragma unroll
            for (int nt = 0; nt < 8; nt++) {
                int c0 = colb + nt*8, c1 = c0 + 1;
                if (c0 > r0) s[nt][0] = -1e30f;
                if (c1 > r0) s[nt][1] = -1e30f;
                if (c0 > r1) s[nt][2] = -1e30f;
                if (c1 > r1) s[nt][3] = -1e30f;
            }
        }

        // ---- online softmax (base 2) ----
        float rm0 = -1e30f, rm1 = -1e30f;
        #pragma unroll
        for (int nt = 0; nt < 8; nt++) {
            rm0 = fmaxf(rm0, fmaxf(s[nt][0], s[nt][1]));
            rm1 = fmaxf(rm1, fmaxf(s[nt][2], s[nt][3]));
        }
        rm0 = fmaxf(rm0, __shfl_xor_sync(0xffffffffu, rm0, 1));
        rm0 = fmaxf(rm0, __shfl_xor_sync(0xffffffffu, rm0, 2));
        rm1 = fmaxf(rm1, __shfl_xor_sync(0xffffffffu, rm1, 1));
        rm1 = fmaxf(rm1, __shfl_xor_sync(0xffffffffu, rm1, 2));
        float mn0 = fmaxf(m0, rm0), mn1 = fmaxf(m1, rm1);
        float corr0 = ex2(m0 - mn0), corr1 = ex2(m1 - mn1);
        m0 = mn0; m1 = mn1;
        float ps0 = 0.f, ps1 = 0.f;
        #pragma unroll
        for (int nt = 0; nt < 8; nt++) {
            s[nt][0] = ex2(s[nt][0] - mn0); ps0 += s[nt][0];
            s[nt][1] = ex2(s[nt][1] - mn0); ps0 += s[nt][1];
            s[nt][2] = ex2(s[nt][2] - mn1); ps1 += s[nt][2];
            s[nt][3] = ex2(s[nt][3] - mn1); ps1 += s[nt][3];
        }
        l0 = l0*corr0 + ps0;
        l1 = l1*corr1 + ps1;
        #pragma unroll
        for (int nt = 0; nt < 8; nt++) {
            o[nt][0] *= corr0; o[nt][1] *= corr0;
            o[nt][2] *= corr1; o[nt][3] *= corr1;
        }

        // ---- O += P V  (P C-frags -> A-frags via quad shuffles) ----
        const int srcA = (lane & ~3) | (c >> 1);
        const int srcB = srcA + 2;
        const bool odd = (c & 1);
        #pragma unroll
        for (int jt = 0; jt < 8; jt++) {
            u32 p0 = tf32u(s[jt][0]), p1 = tf32u(s[jt][1]);
            u32 p2 = tf32u(s[jt][2]), p3 = tf32u(s[jt][3]);
            u32 x0 = __shfl_sync(0xffffffffu, p0, srcA);
            u32 x1 = __shfl_sync(0xffffffffu, p1, srcA);
            u32 x2 = __shfl_sync(0xffffffffu, p2, srcA);
            u32 x3 = __shfl_sync(0xffffffffu, p3, srcA);
            u32 y0 = __shfl_sync(0xffffffffu, p0, srcB);
            u32 y1 = __shfl_sync(0xffffffffu, p1, srcB);
            u32 y2 = __shfl_sync(0xffffffffu, p2, srcB);
            u32 y3 = __shfl_sync(0xffffffffu, p3, srcB);
            u32 pa0 = odd ? x1 : x0;   // P[g,   jt*8+c  ]
            u32 pa1 = odd ? x3 : x2;   // P[g+8, jt*8+c  ]
            u32 pa2 = odd ? y1 : y0;   // P[g,   jt*8+c+4]
            u32 pa3 = odd ? y3 : y2;   // P[g+8, jt*8+c+4]
            #pragma unroll
            for (int nt = 0; nt < 8; nt++) {
                uint2 bb = *(const uint2*)(Vsh + (nt*8+g)*LSTRIDE + jt*8 + 2*c);
                MMA_TF32(o[nt], pa0, pa1, pa2, pa3, bb.x, bb.y);
            }
        }
    }

    // ---- epilogue: finish l across quad, normalize, store ----
    l0 += __shfl_xor_sync(0xffffffffu, l0, 1);
    l0 += __shfl_xor_sync(0xffffffffu, l0, 2);
    l1 += __shfl_xor_sync(0xffffffffu, l1, 1);
    l1 += __shfl_xor_sync(0xffffffffu, l1, 2);
    const float inv0 = 1.f/l0, inv1 = 1.f/l1;
    float* Ob = g_A + ((size_t)b*T_)*D_ + h*DH_;
    const int r0 = qw + g, r1 = r0 + 8;
    #pragma unroll
    for (int nt = 0; nt < 8; nt++) {
        int cc = nt*8 + 2*c;
        *(float2*)(Ob + (size_t)r0*D_ + cc) = make_float2(o[nt][0]*inv0, o[nt][1]*inv0);
        *(float2*)(Ob + (size_t)r1*D_ + cc) = make_float2(o[nt][2]*inv1, o[nt][3]*inv1);
    }
}

// ----------------------------------------------------------------------------
// Kernel 3: output projection, tf32 mma GEMM: out = g_A @ Wo + bo
// grid (32,16); CTA 128 thr = 4 warps x 2 m-tiles; 128x64 tile, K-chunks of 64.
// ----------------------------------------------------------------------------
__global__ __launch_bounds__(128, 4) void oproj_kernel(
    const float* __restrict__ Wo, const float* __restrict__ bo,
    float* __restrict__ out)
{
    extern __shared__ float sm[];
    float* Ash = sm;                  // 128 x 74, tf32, col-interleaved
    float* Bsh = sm + 128*LSTRIDE;    // 64 x 74 = WoT [n][kperm], tf32

    const int tid = threadIdx.x;
    const int w = tid >> 5, lane = tid & 31;
    const int g = lane >> 2, c = lane & 3;
    const int r0 = blockIdx.x*128;
    const int n0 = blockIdx.y*64;

    float o[2][8][4];
    #pragma unroll
    for (int mt = 0; mt < 2; mt++)
        #pragma unroll
        for (int nt = 0; nt < 8; nt++)
            o[mt][nt][0]=o[mt][nt][1]=o[mt][nt][2]=o[mt][nt][3]=0.f;

    const int krow = tid >> 1, nh = (tid & 1)*32;
    const int kp = ((krow>>3)<<3) + ((krow&3)<<1) + ((krow>>2)&1);

    for (int k0 = 0; k0 < D_; k0 += 64) {
        __syncthreads();
        {   // A tile: one row per thread
            const float4* src = (const float4*)(g_A + (size_t)(r0+tid)*D_ + k0);
            float* dst = Ash + tid*LSTRIDE;
            #pragma unroll
            for (int i4 = 0; i4 < 16; i4++) {
                float4 v = src[i4];
                int e0 = i4*4;
                int bb = ((e0>>3)<<3) + ((e0>>2)&1);
                dst[bb+0] = tf32f(v.x); dst[bb+2] = tf32f(v.y);
                dst[bb+4] = tf32f(v.z); dst[bb+6] = tf32f(v.w);
            }
        }
        {   // B tile: Wo[k0+krow][n0+nh..] -> Bsh[n][kperm]
            const float4* src = (const float4*)(Wo + (size_t)(k0+krow)*D_ + n0 + nh);
            #pragma unroll
            for (int i4 = 0; i4 < 8; i4++) {
                float4 v = src[i4];
                int nn = nh + i4*4;
                Bsh[(nn+0)*LSTRIDE + kp] = tf32f(v.x);
                Bsh[(nn+1)*LSTRIDE + kp] = tf32f(v.y);
                Bsh[(nn+2)*LSTRIDE + kp] = tf32f(v.z);
                Bsh[(nn+3)*LSTRIDE + kp] = tf32f(v.w);
            }
        }
        __syncthreads();

        const float* abase = Ash + (w*32 + g)*LSTRIDE + 2*c;
        #pragma unroll
        for (int k8 = 0; k8 < 8; k8++) {
            uint2 a02_0 = *(const uint2*)(abase + k8*8);
            uint2 a13_0 = *(const uint2*)(abase +  8*LSTRIDE + k8*8);
            uint2 a02_1 = *(const uint2*)(abase + 16*LSTRIDE + k8*8);
            uint2 a13_1 = *(const uint2*)(abase + 24*LSTRIDE + k8*8);
            #pragma unroll
            for (int nt = 0; nt < 8; nt++) {
                uint2 bb = *(const uint2*)(Bsh + (nt*8+g)*LSTRIDE + k8*8 + 2*c);
                MMA_TF32(o[0][nt], a02_0.x, a13_0.x, a02_0.y, a13_0.y, bb.x, bb.y);
                MMA_TF32(o[1][nt], a02_1.x, a13_1.x, a02_1.y, a13_1.y, bb.x, bb.y);
            }
        }
    }

    #pragma unroll
    for (int mt = 0; mt < 2; mt++) {
        const int rr0 = r0 + w*32 + mt*16 + g;
        #pragma unroll
        for (int nt = 0; nt < 8; nt++) {
            int cc = n0 + nt*8 + 2*c;
            float b0v = bo[cc], b1v = bo[cc+1];
            *(float2*)(out + (size_t)rr0*D_ + cc) =
                make_float2(o[mt][nt][0]+b0v, o[mt][nt][1]+b1v);
            *(float2*)(out + (size_t)(rr0+8)*D_ + cc) =
                make_float2(o[mt][nt][2]+b0v, o[mt][nt][3]+b1v);
        }
    }
}

// ----------------------------------------------------------------------------
extern "C" void kernel_launch(void* const* d_in, const int* in_sizes, int n_in,
                              void* d_out, int out_size)
{
    (void)in_sizes; (void)n_in; (void)out_size;
    const float* x  = (const float*)d_in[0];
    const float* Wq = (const float*)d_in[1];
    const float* bq = (const float*)d_in[2];
    const float* Wk = (const float*)d_in[3];
    const float* bk = (const float*)d_in[4];
    const float* Wv = (const float*)d_in[5];
    const float* bv = (const float*)d_in[6];
    const float* Wo = (const float*)d_in[7];
    const float* bo = (const float*)d_in[8];
    float* out = (float*)d_out;

    const int qkv_smem   = 192*LSTRIDE*4;   // 56832 B
    const int attn_smem  = 256*LSTRIDE*4;   // 75776 B
    const int oproj_smem = 192*LSTRIDE*4;   // 56832 B
    cudaFuncSetAttribute(qkv_kernel,   cudaFuncAttributeMaxDynamicSharedMemorySize, qkv_smem);
    cudaFuncSetAttribute(attn_kernel,  cudaFuncAttributeMaxDynamicSharedMemorySize, attn_smem);
    cudaFuncSetAttribute(oproj_kernel, cudaFuncAttributeMaxDynamicSharedMemorySize, oproj_smem);

    qkv_kernel<<<dim3(T_/128, H_, B_), 128, qkv_smem>>>(x, Wq, bq, Wk, bk, Wv, bv);
    attn_kernel<<<dim3(T_/128, H_, B_), 256, attn_smem>>>();
    oproj_kernel<<<dim3((B_*T_)/128, D_/64), 128, oproj_smem>>>(Wo, bo, out);
}

// round 7
// speedup vs baseline: 2.8559x; 1.0026x over previous
#include <cuda_runtime.h>
#include <cstdint>

#define B_  2
#define T_  2048
#define D_  1024
#define H_  16
#define DH_ 64
#define SCALE 0.125f   // 1/sqrt(64)
#define QMUL  0.1803368801111136f   // SCALE * log2(e)

typedef unsigned int u32;
typedef unsigned long long u64;

// Scratch (device globals: allocation-free, graph-capture safe)
__device__ float g_Q[B_*H_*T_*DH_];   // [B,H,T,DH]
__device__ float g_K[B_*H_*T_*DH_];
__device__ float g_V[B_*H_*T_*DH_];
__device__ float g_A[B_*T_*D_];       // attention output, head-concat [B,T,D]

// ---- helpers ---------------------------------------------------------------
__device__ __forceinline__ float tf32f(float x) {
    u32 r; asm("cvt.rna.tf32.f32 %0, %1;" : "=r"(r) : "f"(x));
    return __uint_as_float(r);
}
__device__ __forceinline__ u32 tf32u(float x) {
    u32 r; asm("cvt.rna.tf32.f32 %0, %1;" : "=r"(r) : "f"(x));
    return r;
}
__device__ __forceinline__ float ex2(float x) {
    float r; asm("ex2.approx.ftz.f32 %0, %1;" : "=f"(r) : "f"(x));
    return r;
}

#define MMA_TF32(d, a0, a1, a2, a3, b0, b1) \
    asm volatile("mma.sync.aligned.m16n8k8.row.col.f32.tf32.tf32.f32 " \
        "{%0,%1,%2,%3}, {%4,%5,%6,%7}, {%8,%9}, {%0,%1,%2,%3};" \
        : "+f"((d)[0]), "+f"((d)[1]), "+f"((d)[2]), "+f"((d)[3]) \
        : "r"(a0), "r"(a1), "r"(a2), "r"(a3), "r"(b0), "r"(b1))

// Column interleave inside each 8-group: e -> (e>>3)*8 + (e&3)*2 + ((e>>2)&1)
// so that fragment pairs (c, c+4) sit at (2c, 2c+1) -> one LDS.64.
#define LSTRIDE 74

// ----------------------------------------------------------------------------
// Kernel 1: fused per-head QKV projection, tf32 MMA.
// grid (T/128, H, B); 128 thr = 4 warps x 32 rows. One x tile staged once;
// Wq/Wk/Wv cycled through the B buffer across 3 phases.
// ----------------------------------------------------------------------------
__global__ __launch_bounds__(128, 4) void qkv_kernel(
    const float* __restrict__ x,
    const float* __restrict__ Wq, const float* __restrict__ bq,
    const float* __restrict__ Wk, const float* __restrict__ bk,
    const float* __restrict__ Wv, const float* __restrict__ bv)
{
    extern __shared__ float sm[];
    float* Ash = sm;                  // 128 x 74  (x tile, tf32, col-interleaved)
    float* Bsh = sm + 128*LSTRIDE;    // 64 x 74   (W^T: [e][dperm], tf32)

    const int h = blockIdx.y;
    const int b = blockIdx.z;
    const int tid = threadIdx.x;
    const int w = tid >> 5, lane = tid & 31;
    const int g = lane >> 2, c = lane & 3;
    const int t0 = blockIdx.x*128;

    // Stage x tile: one row per thread
    {
        const float4* src = (const float4*)(x + ((size_t)b*T_ + t0 + tid)*D_ + h*DH_);
        float* dst = Ash + tid*LSTRIDE;
        #pragma unroll
        for (int i4 = 0; i4 < 16; i4++) {
            float4 v = src[i4];
            int e0 = i4*4;
            int bb = ((e0>>3)<<3) + ((e0>>2)&1);
            dst[bb+0] = tf32f(v.x); dst[bb+2] = tf32f(v.y);
            dst[bb+4] = tf32f(v.z); dst[bb+6] = tf32f(v.w);
        }
    }

    const int krow = tid >> 1, nh = (tid & 1)*32;
    const int kp = ((krow>>3)<<3) + ((krow&3)<<1) + ((krow>>2)&1);

    for (int m = 0; m < 3; m++) {
        const float* W; const float* bias; float* outp;
        if (m == 0)      { W = Wq; bias = bq; outp = g_Q; }
        else if (m == 1) { W = Wk; bias = bk; outp = g_K; }
        else             { W = Wv; bias = bv; outp = g_V; }
        W += h*DH_*DH_; bias += h*DH_;

        __syncthreads();   // Ash ready (m=0) / previous phase done reading Bsh
        {   // B tile: W[d=krow][e=nh..] -> Bsh[e][dperm]
            const float4* src = (const float4*)(W + (size_t)krow*DH_ + nh);
            #pragma unroll
            for (int i4 = 0; i4 < 8; i4++) {
                float4 v = src[i4];
                int nn = nh + i4*4;
                Bsh[(nn+0)*LSTRIDE + kp] = tf32f(v.x);
                Bsh[(nn+1)*LSTRIDE + kp] = tf32f(v.y);
                Bsh[(nn+2)*LSTRIDE + kp] = tf32f(v.z);
                Bsh[(nn+3)*LSTRIDE + kp] = tf32f(v.w);
            }
        }
        __syncthreads();

        float o[2][8][4];
        #pragma unroll
        for (int mt = 0; mt < 2; mt++)
            #pragma unroll
            for (int nt = 0; nt < 8; nt++)
                o[mt][nt][0]=o[mt][nt][1]=o[mt][nt][2]=o[mt][nt][3]=0.f;

        const float* abase = Ash + (w*32 + g)*LSTRIDE + 2*c;
        #pragma unroll
        for (int k8 = 0; k8 < 8; k8++) {
            uint2 a02_0 = *(const uint2*)(abase + k8*8);
            uint2 a13_0 = *(const uint2*)(abase +  8*LSTRIDE + k8*8);
            uint2 a02_1 = *(const uint2*)(abase + 16*LSTRIDE + k8*8);
            uint2 a13_1 = *(const uint2*)(abase + 24*LSTRIDE + k8*8);
            #pragma unroll
            for (int nt = 0; nt < 8; nt++) {
                uint2 bb = *(const uint2*)(Bsh + (nt*8+g)*LSTRIDE + k8*8 + 2*c);
                MMA_TF32(o[0][nt], a02_0.x, a13_0.x, a02_0.y, a13_0.y, bb.x, bb.y);
                MMA_TF32(o[1][nt], a02_1.x, a13_1.x, a02_1.y, a13_1.y, bb.x, bb.y);
            }
        }

        float* Obase = outp + (((size_t)b*H_ + h)*T_ + t0)*DH_;
        #pragma unroll
        for (int mt = 0; mt < 2; mt++) {
            const int rr0 = w*32 + mt*16 + g;
            #pragma unroll
            for (int nt = 0; nt < 8; nt++) {
                int cc = nt*8 + 2*c;
                float b0v = bias[cc], b1v = bias[cc+1];
                *(float2*)(Obase + (size_t)rr0*DH_ + cc) =
                    make_float2(o[mt][nt][0]+b0v, o[mt][nt][1]+b1v);
                *(float2*)(Obase + (size_t)(rr0+8)*DH_ + cc) =
                    make_float2(o[mt][nt][2]+b0v, o[mt][nt][3]+b1v);
            }
        }
    }
}

// ----------------------------------------------------------------------------
// Kernel 2: causal flash attention with tf32 mma.sync.
// grid (16,16,2) reversed-x; CTA 256 thr = 8 warps x 16 q-rows; K-tiles of 64.
// ----------------------------------------------------------------------------
__global__ __launch_bounds__(256, 2) void attn_kernel()
{
    extern __shared__ float sm[];
    float* Qsh = sm;                  // 128 x 74, tf32, scaled by QMUL
    float* Ksh = sm + 128*LSTRIDE;    // 64 x 74, tf32
    float* Vsh = sm + 192*LSTRIDE;    // 64 x 74, transposed [d][jperm], tf32

    const int h = blockIdx.y, b = blockIdx.z;
    const int bx = (int)gridDim.x - 1 - (int)blockIdx.x;   // heavy-first
    const int q0 = bx*128;
    const int tid = threadIdx.x;
    const int w = tid >> 5, lane = tid & 31;
    const int g = lane >> 2, c = lane & 3;

    const float* Qb = g_Q + (((size_t)b*H_ + h)*T_)*DH_;
    const float* Kb = g_K + (((size_t)b*H_ + h)*T_)*DH_;
    const float* Vb = g_V + (((size_t)b*H_ + h)*T_)*DH_;

    // Stage Q tile (scaled, tf32, column-pair interleaved)
    {
        const int row = tid >> 1, half = (tid & 1)*32;
        const float4* src = (const float4*)(Qb + (size_t)(q0+row)*DH_ + half);
        float* dst = Qsh + row*LSTRIDE;
        #pragma unroll
        for (int i = 0; i < 8; i++) {
            float4 v = src[i];
            int e0 = half + i*4;
            int base = ((e0>>3)<<3) + ((e0>>2)&1);
            dst[base+0] = tf32f(v.x*QMUL);
            dst[base+2] = tf32f(v.y*QMUL);
            dst[base+4] = tf32f(v.z*QMUL);
            dst[base+6] = tf32f(v.w*QMUL);
        }
    }

    const int qw = q0 + w*16;           // warp's first q row (global)
    float s[8][4];
    float o[8][4];
    #pragma unroll
    for (int nt = 0; nt < 8; nt++) { o[nt][0]=o[nt][1]=o[nt][2]=o[nt][3]=0.f; }
    float m0 = -1e30f, m1 = -1e30f, l0 = 0.f, l1 = 0.f;

    const int nkt = bx*2 + 2;
    const int jload = tid >> 2, qq = tid & 3;
    const int jp = ((jload>>3)<<3) + ((jload&3)<<1) + ((jload>>2)&1);

    for (int kt = 0; kt < nkt; kt++) {
        __syncthreads();
        // load K (interleaved) and V (transposed+interleaved) tiles, cvt tf32
        {
            const float* krow = Kb + (size_t)(kt*64 + jload)*DH_ + qq*16;
            const float* vrow = Vb + (size_t)(kt*64 + jload)*DH_ + qq*16;
            float* kdst = Ksh + jload*LSTRIDE;
            #pragma unroll
            for (int i4 = 0; i4 < 4; i4++) {
                float4 kv = ((const float4*)krow)[i4];
                float4 vv = ((const float4*)vrow)[i4];
                int e0 = qq*16 + i4*4;
                int kb = ((e0>>3)<<3) + ((e0>>2)&1);
                kdst[kb+0] = tf32f(kv.x); kdst[kb+2] = tf32f(kv.y);
                kdst[kb+4] = tf32f(kv.z); kdst[kb+6] = tf32f(kv.w);
                Vsh[(e0+0)*LSTRIDE + jp] = tf32f(vv.x);
                Vsh[(e0+1)*LSTRIDE + jp] = tf32f(vv.y);
                Vsh[(e0+2)*LSTRIDE + jp] = tf32f(vv.z);
                Vsh[(e0+3)*LSTRIDE + jp] = tf32f(vv.w);
            }
        }
        __syncthreads();

        if (kt*64 > qw + 15) continue;   // tile fully above diagonal for warp

        // ---- S = Q K^T (scores already in log2 domain via QMUL) ----
        #pragma unroll
        for (int nt = 0; nt < 8; nt++) { s[nt][0]=s[nt][1]=s[nt][2]=s[nt][3]=0.f; }
        const float* qbase = Qsh + (w*16 + g)*LSTRIDE + 2*c;
        #pragma unroll
        for (int k8 = 0; k8 < 8; k8++) {
            uint2 a02 = *(const uint2*)(qbase + k8*8);
            uint2 a13 = *(const uint2*)(qbase + 8*LSTRIDE + k8*8);
            #pragma unroll
            for (int nt = 0; nt < 8; nt++) {
                uint2 bb = *(const uint2*)(Ksh + (nt*8+g)*LSTRIDE + k8*8 + 2*c);
                MMA_TF32(s[nt], a02.x, a13.x, a02.y, a13.y, bb.x, bb.y);
            }
        }

        // ---- causal mask (only near-diagonal tiles) ----
        const int r0 = qw + g, r1 = r0 + 8;
        if (kt*64 + 63 > qw) {
            const int colb = kt*64 + 2*c;
            #pragma unroll
            for (int nt = 0; nt < 8; nt++) {
                int c0 = colb + nt*8, c1 = c0 + 1;
                if (c0 > r0) s[nt][0] = -1e30f;
                if (c1 > r0) s[nt][1] = -1e30f;
                if (c0 > r1) s[nt][2] = -1e30f;
                if (c1 > r1) s[nt][3] = -1e30f;
            }
        }

        // ---- online softmax (base 2) ----
        float rm0 = -1e30f, rm1 = -1e30f;
        #pragma unroll
        for (int nt = 0; nt < 8; nt++) {
            rm0 = fmaxf(rm0, fmaxf(s[nt][0], s[nt][1]));
            rm1 = fmaxf(rm1, fmaxf(s[nt][2], s[nt][3]));
        }
        rm0 = fmaxf(rm0, __shfl_xor_sync(0xffffffffu, rm0, 1));
        rm0 = fmaxf(rm0, __shfl_xor_sync(0xffffffffu, rm0, 2));
        rm1 = fmaxf(rm1, __shfl_xor_sync(0xffffffffu, rm1, 1));
        rm1 = fmaxf(rm1, __shfl_xor_sync(0xffffffffu, rm1, 2));
        float mn0 = fmaxf(m0, rm0), mn1 = fmaxf(m1, rm1);
        float corr0 = ex2(m0 - mn0), corr1 = ex2(m1 - mn1);
        m0 = mn0; m1 = mn1;
        float ps0 = 0.f, ps1 = 0.f;
        #pragma unroll
        for (int nt = 0; nt < 8; nt++) {
            s[nt][0] = ex2(s[nt][0] - mn0); ps0 += s[nt][0];
            s[nt][1] = ex2(s[nt][1] - mn0); ps0 += s[nt][1];
            s[nt][2] = ex2(s[nt][2] - mn1); ps1 += s[nt][2];
            s[nt][3] = ex2(s[nt][3] - mn1); ps1 += s[nt][3];
        }
        l0 = l0*corr0 + ps0;
        l1 = l1*corr1 + ps1;
        #pragma unroll
        for (int nt = 0; nt < 8; nt++) {
            o[nt][0] *= corr0; o[nt][1] *= corr0;
            o[nt][2] *= corr1; o[nt][3] *= corr1;
        }

        // ---- O += P V  (P C-frags -> A-frags via quad shuffles) ----
        const int srcA = (lane & ~3) | (c >> 1);
        const int srcB = srcA + 2;
        const bool odd = (c & 1);
        #pragma unroll
        for (int jt = 0; jt < 8; jt++) {
            u32 p0 = tf32u(s[jt][0]), p1 = tf32u(s[jt][1]);
            u32 p2 = tf32u(s[jt][2]), p3 = tf32u(s[jt][3]);
            u32 x0 = __shfl_sync(0xffffffffu, p0, srcA);
            u32 x1 = __shfl_sync(0xffffffffu, p1, srcA);
            u32 x2 = __shfl_sync(0xffffffffu, p2, srcA);
            u32 x3 = __shfl_sync(0xffffffffu, p3, srcA);
            u32 y0 = __shfl_sync(0xffffffffu, p0, srcB);
            u32 y1 = __shfl_sync(0xffffffffu, p1, srcB);
            u32 y2 = __shfl_sync(0xffffffffu, p2, srcB);
            u32 y3 = __shfl_sync(0xffffffffu, p3, srcB);
            u32 pa0 = odd ? x1 : x0;   // P[g,   jt*8+c  ]
            u32 pa1 = odd ? x3 : x2;   // P[g+8, jt*8+c  ]
            u32 pa2 = odd ? y1 : y0;   // P[g,   jt*8+c+4]
            u32 pa3 = odd ? y3 : y2;   // P[g+8, jt*8+c+4]
            #pragma unroll
            for (int nt = 0; nt < 8; nt++) {
                uint2 bb = *(const uint2*)(Vsh + (nt*8+g)*LSTRIDE + jt*8 + 2*c);
                MMA_TF32(o[nt], pa0, pa1, pa2, pa3, bb.x, bb.y);
            }
        }
    }

    // ---- epilogue: finish l across quad, normalize, store ----
    l0 += __shfl_xor_sync(0xffffffffu, l0, 1);
    l0 += __shfl_xor_sync(0xffffffffu, l0, 2);
    l1 += __shfl_xor_sync(0xffffffffu, l1, 1);
    l1 += __shfl_xor_sync(0xffffffffu, l1, 2);
    const float inv0 = 1.f/l0, inv1 = 1.f/l1;
    float* Ob = g_A + ((size_t)b*T_)*D_ + h*DH_;
    const int r0 = qw + g, r1 = r0 + 8;
    #pragma unroll
    for (int nt = 0; nt < 8; nt++) {
        int cc = nt*8 + 2*c;
        *(float2*)(Ob + (size_t)r0*D_ + cc) = make_float2(o[nt][0]*inv0, o[nt][1]*inv0);
        *(float2*)(Ob + (size_t)r1*D_ + cc) = make_float2(o[nt][2]*inv1, o[nt][3]*inv1);
    }
}

// ----------------------------------------------------------------------------
// Kernel 3: output projection, tf32 mma GEMM: out = g_A @ Wo + bo
// grid (32,16); CTA 128 thr = 4 warps x 2 m-tiles; 128x64 tile, K-chunks of 64.
// ----------------------------------------------------------------------------
__global__ __launch_bounds__(128, 4) void oproj_kernel(
    const float* __restrict__ Wo, const float* __restrict__ bo,
    float* __restrict__ out)
{
    extern __shared__ float sm[];
    float* Ash = sm;                  // 128 x 74, tf32, col-interleaved
    float* Bsh = sm + 128*LSTRIDE;    // 64 x 74 = WoT [n][kperm], tf32

    const int tid = threadIdx.x;
    const int w = tid >> 5, lane = tid & 31;
    const int g = lane >> 2, c = lane & 3;
    const int r0 = blockIdx.x*128;
    const int n0 = blockIdx.y*64;

    float o[2][8][4];
    #pragma unroll
    for (int mt = 0; mt < 2; mt++)
        #pragma unroll
        for (int nt = 0; nt < 8; nt++)
            o[mt][nt][0]=o[mt][nt][1]=o[mt][nt][2]=o[mt][nt][3]=0.f;

    const int krow = tid >> 1, nh = (tid & 1)*32;
    const int kp = ((krow>>3)<<3) + ((krow&3)<<1) + ((krow>>2)&1);

    for (int k0 = 0; k0 < D_; k0 += 64) {
        __syncthreads();
        {   // A tile: one row per thread
            const float4* src = (const float4*)(g_A + (size_t)(r0+tid)*D_ + k0);
            float* dst = Ash + tid*LSTRIDE;
            #pragma unroll
            for (int i4 = 0; i4 < 16; i4++) {
                float4 v = src[i4];
                int e0 = i4*4;
                int bb = ((e0>>3)<<3) + ((e0>>2)&1);
                dst[bb+0] = tf32f(v.x); dst[bb+2] = tf32f(v.y);
                dst[bb+4] = tf32f(v.z); dst[bb+6] = tf32f(v.w);
            }
        }
        {   // B tile: Wo[k0+krow][n0+nh..] -> Bsh[n][kperm]
            const float4* src = (const float4*)(Wo + (size_t)(k0+krow)*D_ + n0 + nh);
            #pragma unroll
            for (int i4 = 0; i4 < 8; i4++) {
                float4 v = src[i4];
                int nn = nh + i4*4;
                Bsh[(nn+0)*LSTRIDE + kp] = tf32f(v.x);
                Bsh[(nn+1)*LSTRIDE + kp] = tf32f(v.y);
                Bsh[(nn+2)*LSTRIDE + kp] = tf32f(v.z);
                Bsh[(nn+3)*LSTRIDE + kp] = tf32f(v.w);
            }
        }
        __syncthreads();

        const float* abase = Ash + (w*32 + g)*LSTRIDE + 2*c;
        #pragma unroll
        for (int k8 = 0; k8 < 8; k8++) {
            uint2 a02_0 = *(const uint2*)(abase + k8*8);
            uint2 a13_0 = *(const uint2*)(abase +  8*LSTRIDE + k8*8);
            uint2 a02_1 = *(const uint2*)(abase + 16*LSTRIDE + k8*8);
            uint2 a13_1 = *(const uint2*)(abase + 24*LSTRIDE + k8*8);
            #pragma unroll
            for (int nt = 0; nt < 8; nt++) {
                uint2 bb = *(const uint2*)(Bsh + (nt*8+g)*LSTRIDE + k8*8 + 2*c);
                MMA_TF32(o[0][nt], a02_0.x, a13_0.x, a02_0.y, a13_0.y, bb.x, bb.y);
                MMA_TF32(o[1][nt], a02_1.x, a13_1.x, a02_1.y, a13_1.y, bb.x, bb.y);
            }
        }
    }

    #pragma unroll
    for (int mt = 0; mt < 2; mt++) {
        const int rr0 = r0 + w*32 + mt*16 + g;
        #pragma unroll
        for (int nt = 0; nt < 8; nt++) {
            int cc = n0 + nt*8 + 2*c;
            float b0v = bo[cc], b1v = bo[cc+1];
            *(float2*)(out + (size_t)rr0*D_ + cc) =
                make_float2(o[mt][nt][0]+b0v, o[mt][nt][1]+b1v);
            *(float2*)(out + (size_t)(rr0+8)*D_ + cc) =
                make_float2(o[mt][nt][2]+b0v, o[mt][nt][3]+b1v);
        }
    }
}

// ----------------------------------------------------------------------------
extern "C" void kernel_launch(void* const* d_in, const int* in_sizes, int n_in,
                              void* d_out, int out_size)
{
    (void)in_sizes; (void)n_in; (void)out_size;
    const float* x  = (const float*)d_in[0];
    const float* Wq = (const float*)d_in[1];
    const float* bq = (const float*)d_in[2];
    const float* Wk = (const float*)d_in[3];
    const float* bk = (const float*)d_in[4];
    const float* Wv = (const float*)d_in[5];
    const float* bv = (const float*)d_in[6];
    const float* Wo = (const float*)d_in[7];
    const float* bo = (const float*)d_in[8];
    float* out = (float*)d_out;

    const int qkv_smem   = 192*LSTRIDE*4;   // 56832 B
    const int attn_smem  = 256*LSTRIDE*4;   // 75776 B
    const int oproj_smem = 192*LSTRIDE*4;   // 56832 B
    cudaFuncSetAttribute(qkv_kernel,   cudaFuncAttributeMaxDynamicSharedMemorySize, qkv_smem);
    cudaFuncSetAttribute(attn_kernel,  cudaFuncAttributeMaxDynamicSharedMemorySize, attn_smem);
    cudaFuncSetAttribute(oproj_kernel, cudaFuncAttributeMaxDynamicSharedMemorySize, oproj_smem);

    qkv_kernel<<<dim3(T_/128, H_, B_), 128, qkv_smem>>>(x, Wq, bq, Wk, bk, Wv, bv);
    attn_kernel<<<dim3(T_/128, H_, B_), 256, attn_smem>>>();
    oproj_kernel<<<dim3((B_*T_)/128, D_/64), 128, oproj_smem>>>(Wo, bo, out);
}